// round 12
// baseline (speedup 1.0000x reference)
#include <cuda_runtime.h>
#include <cuda_bf16.h>
#include <cstdint>
#include <math.h>

#define SS 512
#define BB 32
#define DD 128
#define HH 512
#define G4 2048
// output offsets
#define OFF_PADE 0u
#define OFF_PROB 8388608u
#define OFF_WW   8404992u
#define OFF_WO   16793600u

// ---------------- scratch (__device__ globals; no allocation) ----------------
__device__ __align__(16) float    g_preF[(size_t)SS * BB * G4];
__device__ __align__(16) float    g_preB[(size_t)SS * BB * G4];
__device__ __align__(16) float    g_out0[(size_t)SS * BB * 2 * HH];
__device__ __align__(16) float    g_out1[(size_t)SS * BB * 2 * HH];
__device__ __align__(16) float    g_h[2 * 2 * 2 * HH * BB]; // [layer][dir][buf][k][b]
__device__ unsigned g_ctr[4];
__device__ float    g_sq[BB * SS];
__device__ __align__(16) float    g_pd[(size_t)BB * SS * SS];
__device__ float    g_bsum[2048];
__device__ double   g_sum;

__global__ void init_kernel() {
    int i = blockIdx.x * blockDim.x + threadIdx.x;
    if (i < 2 * 2 * 2 * HH * BB) g_h[i] = 0.0f;
    if (i < 4) g_ctr[i] = 0u;
    if (i == 0) g_sum = 0.0;
}

// ---- SGEMM: C[M=16384,N=2048] = A[M,K] @ W[N,K]^T + bih + bhh (rev flips s) ----
__global__ __launch_bounds__(256) void gemm_pre_kernel(
    const float* __restrict__ A, const float* __restrict__ W,
    const float* __restrict__ bih, const float* __restrict__ bhh,
    float* __restrict__ C, int K, int rev)
{
    __shared__ __align__(16) float As[16][132];
    __shared__ __align__(16) float Bs[16][132];
    const int tid = threadIdx.x;
    const int n0 = blockIdx.x * 128;
    const int m0 = blockIdx.y * 128;
    const int tx = tid & 15, ty = tid >> 4;

    float acc[8][8];
#pragma unroll
    for (int i = 0; i < 8; i++)
#pragma unroll
        for (int j = 0; j < 8; j++) acc[i][j] = 0.0f;

    for (int k0 = 0; k0 < K; k0 += 16) {
#pragma unroll
        for (int r = 0; r < 2; r++) {
            int idx = tid + r * 256;
            int m = idx >> 2;
            int k4 = (idx & 3) * 4;
            int mg = m0 + m;
            int row = mg;
            if (rev) { int s = mg >> 5, b = mg & 31; row = ((SS - 1 - s) << 5) + b; }
            float4 va = *reinterpret_cast<const float4*>(&A[(size_t)row * K + k0 + k4]);
            As[k4 + 0][m] = va.x; As[k4 + 1][m] = va.y;
            As[k4 + 2][m] = va.z; As[k4 + 3][m] = va.w;
            float4 vb = *reinterpret_cast<const float4*>(&W[(size_t)(n0 + m) * K + k0 + k4]);
            Bs[k4 + 0][m] = vb.x; Bs[k4 + 1][m] = vb.y;
            Bs[k4 + 2][m] = vb.z; Bs[k4 + 3][m] = vb.w;
        }
        __syncthreads();
#pragma unroll
        for (int kk = 0; kk < 16; kk++) {
            float4 a0 = *reinterpret_cast<const float4*>(&As[kk][ty * 4]);
            float4 a1 = *reinterpret_cast<const float4*>(&As[kk][ty * 4 + 64]);
            float4 b0 = *reinterpret_cast<const float4*>(&Bs[kk][tx * 4]);
            float4 b1 = *reinterpret_cast<const float4*>(&Bs[kk][tx * 4 + 64]);
            float av[8] = {a0.x, a0.y, a0.z, a0.w, a1.x, a1.y, a1.z, a1.w};
            float bv[8] = {b0.x, b0.y, b0.z, b0.w, b1.x, b1.y, b1.z, b1.w};
#pragma unroll
            for (int i = 0; i < 8; i++)
#pragma unroll
                for (int j = 0; j < 8; j++) acc[i][j] += av[i] * bv[j];
        }
        __syncthreads();
    }

    float bias[8];
#pragma unroll
    for (int j = 0; j < 8; j++) {
        int n = n0 + tx * 4 + (j & 3) + ((j >> 2) << 6);
        bias[j] = bih[n] + bhh[n];
    }
#pragma unroll
    for (int i = 0; i < 8; i++) {
        int mg = m0 + ty * 4 + (i & 3) + ((i >> 2) << 6);
        float* crow = C + (size_t)mg * G4 + n0 + tx * 4;
        float4 v0 = make_float4(acc[i][0] + bias[0], acc[i][1] + bias[1],
                                acc[i][2] + bias[2], acc[i][3] + bias[3]);
        float4 v1 = make_float4(acc[i][4] + bias[4], acc[i][5] + bias[5],
                                acc[i][6] + bias[6], acc[i][7] + bias[7]);
        *reinterpret_cast<float4*>(crow) = v0;
        *reinterpret_cast<float4*>(crow + 64) = v1;
    }
}

// ---------------- persistent bidirectional LSTM layer ----------------
__device__ __forceinline__ float sigf(float x) { return 1.0f / (1.0f + expf(-x)); }

__global__ __launch_bounds__(256) void lstm_kernel(
    const float* __restrict__ preF, const float* __restrict__ preB,
    const float* __restrict__ whhF, const float* __restrict__ whhB,
    float* __restrict__ out, float* __restrict__ hbase,
    unsigned* __restrict__ ctr)
{
    extern __shared__ float smf[];
    float* ws   = smf;                 // [512 k][32 nl]
    float* hs   = smf + HH * BB;       // [512 k][32 b]
    float* gbuf = smf + 2 * HH * BB;   // [32 nl][33]

    const int tid = threadIdx.x;
    const int dir = blockIdx.x >> 6;
    const int blk = blockIdx.x & 63;
    const int j0  = blk * 8;

    const float* pre = dir ? preB : preF;
    const float* whh = dir ? whhB : whhF;
    float* hb = hbase + dir * (2 * HH * BB);
    unsigned* myctr = ctr + dir;

    const int nl = tid & 31;
    const int bg = tid >> 5;
    const int ng = (nl >> 3) * HH + j0 + (nl & 7);

    for (int i = tid; i < HH * 32; i += 256) {
        int w_nl = i >> 9;
        int k    = i & 511;
        int w_ng = (w_nl >> 3) * HH + j0 + (w_nl & 7);
        ws[k * 32 + w_nl] = whh[(size_t)w_ng * HH + k];
    }

    const int uj = tid >> 5;
    const int ub = tid & 31;
    float c_reg = 0.0f;
    __syncthreads();

    for (int s = 0; s < SS; s++) {
        const float* hsrc = hb + (s & 1) * (HH * BB);
        float*       hdst = hb + ((s + 1) & 1) * (HH * BB);

        for (int i = tid * 4; i < HH * BB; i += 1024)
            *reinterpret_cast<float4*>(&hs[i]) =
                *reinterpret_cast<const float4*>(&hsrc[i]);
        __syncthreads();

        const float* prep = pre + (size_t)s * (BB * G4) + ng;
        float a0 = prep[(size_t)(bg * 4 + 0) * G4];
        float a1 = prep[(size_t)(bg * 4 + 1) * G4];
        float a2 = prep[(size_t)(bg * 4 + 2) * G4];
        float a3 = prep[(size_t)(bg * 4 + 3) * G4];
#pragma unroll 8
        for (int k = 0; k < HH; k++) {
            float4 h4 = *reinterpret_cast<const float4*>(&hs[k * 32 + bg * 4]);
            float  w  = ws[k * 32 + nl];
            a0 += h4.x * w; a1 += h4.y * w; a2 += h4.z * w; a3 += h4.w * w;
        }
        gbuf[nl * 33 + bg * 4 + 0] = a0;
        gbuf[nl * 33 + bg * 4 + 1] = a1;
        gbuf[nl * 33 + bg * 4 + 2] = a2;
        gbuf[nl * 33 + bg * 4 + 3] = a3;
        __syncthreads();

        float gi = gbuf[(uj)      * 33 + ub];
        float gf = gbuf[(8 + uj)  * 33 + ub];
        float gg = gbuf[(16 + uj) * 33 + ub];
        float go = gbuf[(24 + uj) * 33 + ub];
        c_reg = sigf(gf) * c_reg + sigf(gi) * tanhf(gg);
        float hv = sigf(go) * tanhf(c_reg);

        hdst[(j0 + uj) * 32 + ub] = hv;
        int so = dir ? (SS - 1 - s) : s;
        out[((size_t)so * BB + ub) * (2 * HH) + dir * HH + j0 + uj] = hv;

        __threadfence();
        __syncthreads();
        if (tid == 0) {
            atomicAdd(myctr, 1u);
            unsigned target = (unsigned)(64 * (s + 1));
            while (*((volatile unsigned*)myctr) < target) { __nanosleep(64); }
        }
        __syncthreads();
        __threadfence();
    }
}

// ---------------- sq[b][s] = ||emb[s][b]||^2 ----------------
__global__ void sq_kernel(const float* __restrict__ emb) {
    int gwarp = (blockIdx.x * blockDim.x + threadIdx.x) >> 5;
    int lane  = threadIdx.x & 31;
    if (gwarp >= SS * BB) return;
    const float* rowp = emb + (size_t)gwarp * DD;
    float ssum = 0.0f;
#pragma unroll
    for (int d = lane; d < DD; d += 32) { float v = rowp[d]; ssum += v * v; }
#pragma unroll
    for (int o = 16; o > 0; o >>= 1) ssum += __shfl_down_sync(0xffffffffu, ssum, o);
    if (lane == 0) {
        int s = gwarp >> 5, b = gwarp & 31;
        g_sq[b * SS + s] = ssum;
    }
}

// ---------------- pd[b][n][m] + per-block sums ----------------
__global__ __launch_bounds__(256) void pd_kernel(const float* __restrict__ emb) {
    __shared__ __align__(16) float Ans[64][68];
    __shared__ __align__(16) float Ams[64][68];
    __shared__ float red[256];
    const int b  = blockIdx.z;
    const int n0 = blockIdx.y * 64;
    const int m0 = blockIdx.x * 64;
    const int tid = threadIdx.x;
    const int tx = tid & 15, ty = tid >> 4;

    float acc[4][4];
#pragma unroll
    for (int i = 0; i < 4; i++)
#pragma unroll
        for (int j = 0; j < 4; j++) acc[i][j] = 0.0f;

    for (int kc = 0; kc < DD; kc += 64) {
#pragma unroll
        for (int r = 0; r < 4; r++) {
            int idx = tid + r * 256;
            int row = idx >> 4;
            int kf  = (idx & 15) * 4;
            float4 vn = *reinterpret_cast<const float4*>(
                &emb[(((size_t)(n0 + row)) * BB + b) * DD + kc + kf]);
            Ans[kf + 0][row] = vn.x; Ans[kf + 1][row] = vn.y;
            Ans[kf + 2][row] = vn.z; Ans[kf + 3][row] = vn.w;
            float4 vm = *reinterpret_cast<const float4*>(
                &emb[(((size_t)(m0 + row)) * BB + b) * DD + kc + kf]);
            Ams[kf + 0][row] = vm.x; Ams[kf + 1][row] = vm.y;
            Ams[kf + 2][row] = vm.z; Ams[kf + 3][row] = vm.w;
        }
        __syncthreads();
#pragma unroll 8
        for (int kk = 0; kk < 64; kk++) {
            float4 an = *reinterpret_cast<const float4*>(&Ans[kk][ty * 4]);
            float4 am = *reinterpret_cast<const float4*>(&Ams[kk][tx * 4]);
            float av[4] = {an.x, an.y, an.z, an.w};
            float bv[4] = {am.x, am.y, am.z, am.w};
#pragma unroll
            for (int i = 0; i < 4; i++)
#pragma unroll
                for (int j = 0; j < 4; j++) acc[i][j] += av[i] * bv[j];
        }
        __syncthreads();
    }

    float sqn[4], sqm[4];
#pragma unroll
    for (int i = 0; i < 4; i++) sqn[i] = g_sq[b * SS + n0 + ty * 4 + i];
#pragma unroll
    for (int j = 0; j < 4; j++) sqm[j] = g_sq[b * SS + m0 + tx * 4 + j];

    float lsum = 0.0f;
#pragma unroll
    for (int i = 0; i < 4; i++) {
        int n = n0 + ty * 4 + i;
        float* prow = g_pd + (((size_t)b * SS) + n) * SS + m0 + tx * 4;
        float4 v;
        float* vp = &v.x;
#pragma unroll
        for (int j = 0; j < 4; j++) {
            float d2 = fmaxf(sqn[i] + sqm[j] - 2.0f * acc[i][j], 0.0f);
            float pdv = (d2 > 0.0f) ? sqrtf(d2) : 0.0f;
            vp[j] = pdv;
            lsum += pdv;
        }
        *reinterpret_cast<float4*>(prow) = v;
    }

    red[tid] = lsum;
    __syncthreads();
    for (int o = 128; o > 0; o >>= 1) {
        if (tid < o) red[tid] += red[tid + o];
        __syncthreads();
    }
    if (tid == 0)
        g_bsum[blockIdx.z * 64 + blockIdx.y * 8 + blockIdx.x] = red[0];
}

__global__ void sum_reduce_kernel() {
    __shared__ double red[256];
    int tid = threadIdx.x;
    double s = 0.0;
    for (int i = tid; i < 2048; i += 256) s += (double)g_bsum[i];
    red[tid] = s;
    __syncthreads();
    for (int o = 128; o > 0; o >>= 1) {
        if (tid < o) red[tid] += red[tid + o];
        __syncthreads();
    }
    if (tid == 0) g_sum = red[0];
}

__global__ void ww_final_kernel(float* __restrict__ outp) {
    size_t i = (size_t)blockIdx.x * blockDim.x + threadIdx.x;
    if (i >= (size_t)BB * SS * SS) return;
    float mean = (float)(g_sum / (double)((size_t)BB * SS * SS));
    float dis = mean - g_pd[i];
    float v = 1.0f / (1.0f + expf(-dis));
    outp[OFF_WW + i] = (v < 0.5f) ? 0.0f : v;
}

// word_operator: sigmoid(emb1 . op_emb^T), thresholded
__global__ __launch_bounds__(256) void wo_kernel(
    const float* __restrict__ emb, const float* __restrict__ op_emb,
    float* __restrict__ outp)
{
    __shared__ float ops[DD * 32];   // [d][o]
    int tid = threadIdx.x;
    for (int i = tid; i < DD * 32; i += 256) {
        int d = i >> 5, o = i & 31;
        ops[d * 32 + o] = op_emb[o * DD + d];
    }
    __syncthreads();
    int r = tid >> 5, o = tid & 31;
    int gr = blockIdx.x * 8 + r;       // gr = b*S + n
    int b = gr >> 9, n = gr & 511;
    const float* erow = emb + (((size_t)n * BB) + b) * DD;
    float acc = 0.0f;
#pragma unroll 16
    for (int d = 0; d < DD; d++) acc += erow[d] * ops[d * 32 + o];
    float v = 1.0f / (1.0f + expf(-acc));
    outp[OFF_WO + (size_t)gr * 32 + o] = (v < 0.5f) ? 0.0f : v;
}

__global__ void pade_kernel(float* __restrict__ outp) {
    size_t i = (size_t)blockIdx.x * blockDim.x + threadIdx.x;
    if (i >= (size_t)SS * BB * HH) return;
    size_t s = i / (BB * HH);
    size_t r = i % (BB * HH);
    size_t b = r / HH, j = r % HH;
    size_t base = (s * BB + b) * (2 * HH);
    outp[OFF_PADE + i] = g_out1[base + j] + g_out1[base + HH + j];
}

__global__ void prob_kernel(float* __restrict__ outp) {
    int i = blockIdx.x * blockDim.x + threadIdx.x;
    if (i >= BB * HH) return;
    int b = i / HH, j = i % HH;
    outp[OFF_PROB + i] =
        g_out1[(((size_t)(SS - 1) * BB) + b) * (2 * HH) + j] +
        g_out1[((size_t)b) * (2 * HH) + HH + j];
}

// ---------------------------------------------------------------------------
extern "C" void kernel_launch(void* const* d_in, const int* in_sizes, int n_in,
                              void* d_out, int out_size)
{
    const float* emb    = (const float*)d_in[0];
    const float* op_emb = (const float*)d_in[2];
    const float* wih0f = (const float*)d_in[3],  *whh0f = (const float*)d_in[4];
    const float* bih0f = (const float*)d_in[5],  *bhh0f = (const float*)d_in[6];
    const float* wih0b = (const float*)d_in[7],  *whh0b = (const float*)d_in[8];
    const float* bih0b = (const float*)d_in[9],  *bhh0b = (const float*)d_in[10];
    const float* wih1f = (const float*)d_in[11], *whh1f = (const float*)d_in[12];
    const float* bih1f = (const float*)d_in[13], *bhh1f = (const float*)d_in[14];
    const float* wih1b = (const float*)d_in[15], *whh1b = (const float*)d_in[16];
    const float* bih1b = (const float*)d_in[17], *bhh1b = (const float*)d_in[18];
    float* outp = (float*)d_out;

    void *pPreF, *pPreB, *pOut0, *pOut1, *pH, *pCtr;
    cudaGetSymbolAddress(&pPreF, g_preF);
    cudaGetSymbolAddress(&pPreB, g_preB);
    cudaGetSymbolAddress(&pOut0, g_out0);
    cudaGetSymbolAddress(&pOut1, g_out1);
    cudaGetSymbolAddress(&pH,    g_h);
    cudaGetSymbolAddress(&pCtr,  g_ctr);
    float* preF = (float*)pPreF;  float* preB = (float*)pPreB;
    float* out0 = (float*)pOut0;  float* out1 = (float*)pOut1;
    float* hb   = (float*)pH;     unsigned* ctr = (unsigned*)pCtr;

    const int SMEM_LSTM = (2 * HH * BB + 32 * 33) * (int)sizeof(float);
    cudaFuncSetAttribute(lstm_kernel,
        cudaFuncAttributeMaxDynamicSharedMemorySize, SMEM_LSTM);

    init_kernel<<<512, 256>>>();

    dim3 ggrid(16, 128);
    // layer 0 input projections (K = 128)
    gemm_pre_kernel<<<ggrid, 256>>>(emb, wih0f, bih0f, bhh0f, preF, DD, 0);
    gemm_pre_kernel<<<ggrid, 256>>>(emb, wih0b, bih0b, bhh0b, preB, DD, 1);
    lstm_kernel<<<128, 256, SMEM_LSTM>>>(preF, preB, whh0f, whh0b,
                                         out0, hb, ctr);
    // layer 1 input projections (K = 1024)
    gemm_pre_kernel<<<ggrid, 256>>>(out0, wih1f, bih1f, bhh1f, preF, 2 * HH, 0);
    gemm_pre_kernel<<<ggrid, 256>>>(out0, wih1b, bih1b, bhh1b, preB, 2 * HH, 1);
    lstm_kernel<<<128, 256, SMEM_LSTM>>>(preF, preB, whh1f, whh1b,
                                         out1, hb + 2 * 2 * HH * BB, ctr + 2);

    // word_word
    sq_kernel<<<(SS * BB * 32 + 255) / 256, 256>>>(emb);
    dim3 pgrid(8, 8, 32);
    pd_kernel<<<pgrid, 256>>>(emb);
    sum_reduce_kernel<<<1, 256>>>();
    ww_final_kernel<<<32768, 256>>>(outp);

    // word_operator
    wo_kernel<<<2048, 256>>>(emb, op_emb, outp);

    // pade + problem outputs
    pade_kernel<<<32768, 256>>>(outp);
    prob_kernel<<<64, 256>>>(outp);
}

// round 13
// speedup vs baseline: 1.3487x; 1.3487x over previous
#include <cuda_runtime.h>
#include <cuda_bf16.h>
#include <cstdint>
#include <math.h>

#define SS 512
#define BB 32
#define DD 128
#define HH 512
#define G4 2048
#define OFF_PADE 0u
#define OFF_PROB 8388608u
#define OFF_WW   8404992u
#define OFF_WO   16793600u

// ---------------- scratch ----------------
__device__ __align__(16) float    g_preF[(size_t)SS * BB * G4];
__device__ __align__(16) float    g_preB[(size_t)SS * BB * G4];
__device__ __align__(16) float    g_out0[(size_t)SS * BB * 2 * HH];
__device__ __align__(16) float    g_out1[(size_t)SS * BB * 2 * HH];
__device__ __align__(16) float    g_h[2 * 2 * 2 * HH * BB];
__device__ unsigned g_ctr[4];
__device__ float    g_sq[BB * SS];
__device__ __align__(16) float    g_pd[(size_t)BB * SS * SS];
__device__ float    g_bsum[2048];
__device__ double   g_sum;

// ---------------- f32x2 helpers ----------------
__device__ __forceinline__ void fma2(unsigned long long& acc,
                                     unsigned long long a, unsigned long long b) {
    asm("fma.rn.f32x2 %0, %1, %2, %0;" : "+l"(acc) : "l"(a), "l"(b));
}
__device__ __forceinline__ unsigned long long p2(float x, float y) {
    unsigned long long r; asm("mov.b64 %0, {%1,%2};" : "=l"(r) : "f"(x), "f"(y)); return r;
}
__device__ __forceinline__ float2 up2(unsigned long long v) {
    float2 r; asm("mov.b64 {%0,%1}, %2;" : "=f"(r.x), "=f"(r.y) : "l"(v)); return r;
}
__device__ __forceinline__ unsigned long long add2(unsigned long long a,
                                                   unsigned long long b) {
    unsigned long long r; asm("add.rn.f32x2 %0, %1, %2;" : "=l"(r) : "l"(a), "l"(b));
    return r;
}

__global__ void init_kernel() {
    int i = blockIdx.x * blockDim.x + threadIdx.x;
    if (i < 2 * 2 * 2 * HH * BB) g_h[i] = 0.0f;
    if (i < 4) g_ctr[i] = 0u;
    if (i == 0) g_sum = 0.0;
}

// ---- SGEMM (f32x2): C[16384,2048] = A[M,K] @ W[N,K]^T + bih + bhh ----
__global__ __launch_bounds__(256) void gemm_pre_kernel(
    const float* __restrict__ A, const float* __restrict__ W,
    const float* __restrict__ bih, const float* __restrict__ bhh,
    float* __restrict__ C, int K, int rev)
{
    __shared__ __align__(16) float As[16][132];
    __shared__ __align__(16) float Bs[16][132];
    const int tid = threadIdx.x;
    const int n0 = blockIdx.x * 128;
    const int m0 = blockIdx.y * 128;
    const int tx = tid & 15, ty = tid >> 4;

    const int mL = tid >> 2;            // 0..63
    const int k4 = (tid & 3) * 4;
    int rowA0 = m0 + mL, rowA1 = m0 + mL + 64;
    if (rev) {
        rowA0 = ((SS - 1 - (rowA0 >> 5)) << 5) + (rowA0 & 31);
        rowA1 = ((SS - 1 - (rowA1 >> 5)) << 5) + (rowA1 & 31);
    }
    const float* Wp0 = W + (size_t)(n0 + mL) * K + k4;
    const float* Wp1 = W + (size_t)(n0 + mL + 64) * K + k4;
    const float* Ap0 = A + (size_t)rowA0 * K + k4;
    const float* Ap1 = A + (size_t)rowA1 * K + k4;

    unsigned long long accp[8][4];
#pragma unroll
    for (int i = 0; i < 8; i++)
#pragma unroll
        for (int p = 0; p < 4; p++) accp[i][p] = 0ull;

    float4 ra0, ra1, rb0, rb1;
    ra0 = *reinterpret_cast<const float4*>(Ap0);
    ra1 = *reinterpret_cast<const float4*>(Ap1);
    rb0 = *reinterpret_cast<const float4*>(Wp0);
    rb1 = *reinterpret_cast<const float4*>(Wp1);

    for (int k0 = 0; k0 < K; k0 += 16) {
        As[k4 + 0][mL] = ra0.x; As[k4 + 1][mL] = ra0.y;
        As[k4 + 2][mL] = ra0.z; As[k4 + 3][mL] = ra0.w;
        As[k4 + 0][mL + 64] = ra1.x; As[k4 + 1][mL + 64] = ra1.y;
        As[k4 + 2][mL + 64] = ra1.z; As[k4 + 3][mL + 64] = ra1.w;
        Bs[k4 + 0][mL] = rb0.x; Bs[k4 + 1][mL] = rb0.y;
        Bs[k4 + 2][mL] = rb0.z; Bs[k4 + 3][mL] = rb0.w;
        Bs[k4 + 0][mL + 64] = rb1.x; Bs[k4 + 1][mL + 64] = rb1.y;
        Bs[k4 + 2][mL + 64] = rb1.z; Bs[k4 + 3][mL + 64] = rb1.w;
        __syncthreads();
        if (k0 + 16 < K) {
            ra0 = *reinterpret_cast<const float4*>(Ap0 + k0 + 16);
            ra1 = *reinterpret_cast<const float4*>(Ap1 + k0 + 16);
            rb0 = *reinterpret_cast<const float4*>(Wp0 + k0 + 16);
            rb1 = *reinterpret_cast<const float4*>(Wp1 + k0 + 16);
        }
#pragma unroll
        for (int kk = 0; kk < 16; kk++) {
            float4 a0 = *reinterpret_cast<const float4*>(&As[kk][ty * 4]);
            float4 a1 = *reinterpret_cast<const float4*>(&As[kk][ty * 4 + 64]);
            float4 b0 = *reinterpret_cast<const float4*>(&Bs[kk][tx * 4]);
            float4 b1 = *reinterpret_cast<const float4*>(&Bs[kk][tx * 4 + 64]);
            unsigned long long bp0 = p2(b0.x, b0.y), bp1 = p2(b0.z, b0.w);
            unsigned long long bp2 = p2(b1.x, b1.y), bp3 = p2(b1.z, b1.w);
            float av[8] = {a0.x, a0.y, a0.z, a0.w, a1.x, a1.y, a1.z, a1.w};
#pragma unroll
            for (int i = 0; i < 8; i++) {
                unsigned long long ad = p2(av[i], av[i]);
                fma2(accp[i][0], ad, bp0);
                fma2(accp[i][1], ad, bp1);
                fma2(accp[i][2], ad, bp2);
                fma2(accp[i][3], ad, bp3);
            }
        }
        __syncthreads();
    }

    float bias[8];
#pragma unroll
    for (int j = 0; j < 8; j++) {
        int n = n0 + tx * 4 + (j & 3) + ((j >> 2) << 6);
        bias[j] = bih[n] + bhh[n];
    }
#pragma unroll
    for (int i = 0; i < 8; i++) {
        int mg = m0 + ty * 4 + (i & 3) + ((i >> 2) << 6);
        float* crow = C + (size_t)mg * G4 + n0 + tx * 4;
        float2 q0 = up2(accp[i][0]), q1 = up2(accp[i][1]);
        float2 q2 = up2(accp[i][2]), q3 = up2(accp[i][3]);
        float4 v0 = make_float4(q0.x + bias[0], q0.y + bias[1],
                                q1.x + bias[2], q1.y + bias[3]);
        float4 v1 = make_float4(q2.x + bias[4], q2.y + bias[5],
                                q3.x + bias[6], q3.y + bias[7]);
        *reinterpret_cast<float4*>(crow) = v0;
        *reinterpret_cast<float4*>(crow + 64) = v1;
    }
}

// ---------------- persistent bidirectional LSTM (k-split, f32x2) ----------------
__device__ __forceinline__ float sigf(float x) { return 1.0f / (1.0f + expf(-x)); }

#define RED_STRIDE 34

__global__ __launch_bounds__(256) void lstm_kernel(
    const float* __restrict__ preF, const float* __restrict__ preB,
    const float* __restrict__ whhF, const float* __restrict__ whhB,
    float* __restrict__ out, float* __restrict__ hbase,
    unsigned* __restrict__ ctr)
{
    extern __shared__ float smf[];
    float* ws  = smf;                    // [512][32]  ws[k*32+c]
    float* hs  = smf + HH * BB;          // [512][32]  hs[k*32+b]
    float* red = smf + 2 * HH * BB;      // [4*32][RED_STRIDE]

    const int tid = threadIdx.x;
    const int dir = blockIdx.x >> 6;
    const int blk = blockIdx.x & 63;
    const int j0  = blk * 8;

    const float* pre = dir ? preB : preF;
    const float* whh = dir ? whhB : whhF;
    float* hb = hbase + dir * (2 * HH * BB);
    unsigned* myctr = ctr + dir;

    // load Whh slice: ws[k][c] = whh[ng(c)][k]
    for (int i = tid; i < HH * 32; i += 256) {
        int c = i >> 9;
        int k = i & 511;
        int ng = (c >> 3) * HH + j0 + (c & 7);
        ws[k * 32 + c] = whh[(size_t)ng * HH + k];
    }

    // k-loop mapping: 4 k-groups x (8 b-chunks x 8 c-chunks)
    const int kg  = tid >> 6;
    const int t64 = tid & 63;
    const int tb  = (t64 & 7) * 4;
    const int tc  = (t64 >> 3) * 4;
    const int kbeg = kg * 128;
    const int ngb  = (tc >> 3) * HH + j0 + (tc & 7);

    // update mapping
    const int uj = tid >> 5;
    const int ub = tid & 31;
    float c_reg = 0.0f;
    __syncthreads();

    for (int s = 0; s < SS; s++) {
        const float* hsrc = hb + (s & 1) * (HH * BB);
        float*       hdst = hb + ((s + 1) & 1) * (HH * BB);

        // stage h into smem (L2 reads via ldcg)
        for (int i = tid * 4; i < HH * BB; i += 1024) {
            float4 v = __ldcg(reinterpret_cast<const float4*>(&hsrc[i]));
            *reinterpret_cast<float4*>(&hs[i]) = v;
        }
        // prefetch pre (folded into kg==0 partials)
        float4 pv0, pv1, pv2, pv3;
        if (kg == 0) {
            const float* pb = pre + ((size_t)s * BB + tb) * G4 + ngb;
            pv0 = __ldcg(reinterpret_cast<const float4*>(pb));
            pv1 = __ldcg(reinterpret_cast<const float4*>(pb + G4));
            pv2 = __ldcg(reinterpret_cast<const float4*>(pb + 2 * G4));
            pv3 = __ldcg(reinterpret_cast<const float4*>(pb + 3 * G4));
        }
        __syncthreads();

        unsigned long long acc[4][2];
#pragma unroll
        for (int b = 0; b < 4; b++) { acc[b][0] = 0ull; acc[b][1] = 0ull; }

        const float* hp = hs + kbeg * 32 + tb;
        const float* wp = ws + kbeg * 32 + tc;
#pragma unroll 8
        for (int k = 0; k < 128; k++) {
            float4 h4 = *reinterpret_cast<const float4*>(hp);
            ulonglong2 w2 = *reinterpret_cast<const ulonglong2*>(wp);
            unsigned long long hd;
            hd = p2(h4.x, h4.x); fma2(acc[0][0], hd, w2.x); fma2(acc[0][1], hd, w2.y);
            hd = p2(h4.y, h4.y); fma2(acc[1][0], hd, w2.x); fma2(acc[1][1], hd, w2.y);
            hd = p2(h4.z, h4.z); fma2(acc[2][0], hd, w2.x); fma2(acc[2][1], hd, w2.y);
            hd = p2(h4.w, h4.w); fma2(acc[3][0], hd, w2.x); fma2(acc[3][1], hd, w2.y);
            hp += 32; wp += 32;
        }
        if (kg == 0) {
            acc[0][0] = add2(acc[0][0], p2(pv0.x, pv0.y));
            acc[0][1] = add2(acc[0][1], p2(pv0.z, pv0.w));
            acc[1][0] = add2(acc[1][0], p2(pv1.x, pv1.y));
            acc[1][1] = add2(acc[1][1], p2(pv1.z, pv1.w));
            acc[2][0] = add2(acc[2][0], p2(pv2.x, pv2.y));
            acc[2][1] = add2(acc[2][1], p2(pv2.z, pv2.w));
            acc[3][0] = add2(acc[3][0], p2(pv3.x, pv3.y));
            acc[3][1] = add2(acc[3][1], p2(pv3.z, pv3.w));
        }
#pragma unroll
        for (int b = 0; b < 4; b++) {
            unsigned long long* rp = reinterpret_cast<unsigned long long*>(
                &red[(kg * 32 + tb + b) * RED_STRIDE + tc]);
            rp[0] = acc[b][0];
            rp[1] = acc[b][1];
        }
        __syncthreads();

        // gates + cell update; thread owns (uj, ub)
        float gv[4];
#pragma unroll
        for (int g = 0; g < 4; g++) {
            int c = g * 8 + uj;
            gv[g] = (red[(0 * 32 + ub) * RED_STRIDE + c] +
                     red[(1 * 32 + ub) * RED_STRIDE + c]) +
                    (red[(2 * 32 + ub) * RED_STRIDE + c] +
                     red[(3 * 32 + ub) * RED_STRIDE + c]);
        }
        c_reg = sigf(gv[1]) * c_reg + sigf(gv[0]) * tanhf(gv[2]);
        float hv = sigf(gv[3]) * tanhf(c_reg);

        __stcg(&hdst[(j0 + uj) * 32 + ub], hv);
        int so = dir ? (SS - 1 - s) : s;
        __stcg(&out[((size_t)so * BB + ub) * (2 * HH) + dir * HH + j0 + uj], hv);

        // inter-block barrier (tid0 release/acquire, cumulative fences)
        __syncthreads();
        if (tid == 0) {
            __threadfence();
            atomicAdd(myctr, 1u);
            unsigned target = 64u * (unsigned)(s + 1);
            while (*((volatile unsigned*)myctr) < target) { __nanosleep(32); }
            __threadfence();
        }
        __syncthreads();
    }
}

// ---------------- sq ----------------
__global__ void sq_kernel(const float* __restrict__ emb) {
    int gwarp = (blockIdx.x * blockDim.x + threadIdx.x) >> 5;
    int lane  = threadIdx.x & 31;
    if (gwarp >= SS * BB) return;
    const float* rowp = emb + (size_t)gwarp * DD;
    float ssum = 0.0f;
#pragma unroll
    for (int d = lane; d < DD; d += 32) { float v = rowp[d]; ssum += v * v; }
#pragma unroll
    for (int o = 16; o > 0; o >>= 1) ssum += __shfl_down_sync(0xffffffffu, ssum, o);
    if (lane == 0) {
        int s = gwarp >> 5, b = gwarp & 31;
        g_sq[b * SS + s] = ssum;
    }
}

// ---------------- pd + block sums ----------------
__global__ __launch_bounds__(256) void pd_kernel(const float* __restrict__ emb) {
    __shared__ __align__(16) float Ans[64][68];
    __shared__ __align__(16) float Ams[64][68];
    __shared__ float redsm[256];
    const int b  = blockIdx.z;
    const int n0 = blockIdx.y * 64;
    const int m0 = blockIdx.x * 64;
    const int tid = threadIdx.x;
    const int tx = tid & 15, ty = tid >> 4;

    float acc[4][4];
#pragma unroll
    for (int i = 0; i < 4; i++)
#pragma unroll
        for (int j = 0; j < 4; j++) acc[i][j] = 0.0f;

    for (int kc = 0; kc < DD; kc += 64) {
#pragma unroll
        for (int r = 0; r < 4; r++) {
            int idx = tid + r * 256;
            int row = idx >> 4;
            int kf  = (idx & 15) * 4;
            float4 vn = *reinterpret_cast<const float4*>(
                &emb[(((size_t)(n0 + row)) * BB + b) * DD + kc + kf]);
            Ans[kf + 0][row] = vn.x; Ans[kf + 1][row] = vn.y;
            Ans[kf + 2][row] = vn.z; Ans[kf + 3][row] = vn.w;
            float4 vm = *reinterpret_cast<const float4*>(
                &emb[(((size_t)(m0 + row)) * BB + b) * DD + kc + kf]);
            Ams[kf + 0][row] = vm.x; Ams[kf + 1][row] = vm.y;
            Ams[kf + 2][row] = vm.z; Ams[kf + 3][row] = vm.w;
        }
        __syncthreads();
#pragma unroll 8
        for (int kk = 0; kk < 64; kk++) {
            float4 an = *reinterpret_cast<const float4*>(&Ans[kk][ty * 4]);
            float4 am = *reinterpret_cast<const float4*>(&Ams[kk][tx * 4]);
            float av[4] = {an.x, an.y, an.z, an.w};
            float bv[4] = {am.x, am.y, am.z, am.w};
#pragma unroll
            for (int i = 0; i < 4; i++)
#pragma unroll
                for (int j = 0; j < 4; j++) acc[i][j] += av[i] * bv[j];
        }
        __syncthreads();
    }

    float sqn[4], sqm[4];
#pragma unroll
    for (int i = 0; i < 4; i++) sqn[i] = g_sq[b * SS + n0 + ty * 4 + i];
#pragma unroll
    for (int j = 0; j < 4; j++) sqm[j] = g_sq[b * SS + m0 + tx * 4 + j];

    float lsum = 0.0f;
#pragma unroll
    for (int i = 0; i < 4; i++) {
        int n = n0 + ty * 4 + i;
        float* prow = g_pd + (((size_t)b * SS) + n) * SS + m0 + tx * 4;
        float4 v;
        float* vp = &v.x;
#pragma unroll
        for (int j = 0; j < 4; j++) {
            float d2 = fmaxf(sqn[i] + sqm[j] - 2.0f * acc[i][j], 0.0f);
            float pdv = (d2 > 0.0f) ? sqrtf(d2) : 0.0f;
            vp[j] = pdv;
            lsum += pdv;
        }
        *reinterpret_cast<float4*>(prow) = v;
    }

    redsm[tid] = lsum;
    __syncthreads();
    for (int o = 128; o > 0; o >>= 1) {
        if (tid < o) redsm[tid] += redsm[tid + o];
        __syncthreads();
    }
    if (tid == 0)
        g_bsum[blockIdx.z * 64 + blockIdx.y * 8 + blockIdx.x] = redsm[0];
}

__global__ void sum_reduce_kernel() {
    __shared__ double red[256];
    int tid = threadIdx.x;
    double s = 0.0;
    for (int i = tid; i < 2048; i += 256) s += (double)g_bsum[i];
    red[tid] = s;
    __syncthreads();
    for (int o = 128; o > 0; o >>= 1) {
        if (tid < o) red[tid] += red[tid + o];
        __syncthreads();
    }
    if (tid == 0) g_sum = red[0];
}

__device__ __forceinline__ float thresh_sigmoid(float dis) {
    if (dis < -1e-3f) return 0.0f;
    if (dis > 1e-3f)  return 1.0f / (1.0f + __expf(-dis));
    float sv = 1.0f / (1.0f + expf(-dis));
    return (sv < 0.5f) ? 0.0f : sv;
}

__global__ void ww_final_kernel(float* __restrict__ outp) {
    size_t i = (size_t)blockIdx.x * blockDim.x + threadIdx.x;
    if (i >= (size_t)BB * SS * SS) return;
    float mean = (float)(g_sum / (double)((size_t)BB * SS * SS));
    outp[OFF_WW + i] = thresh_sigmoid(mean - g_pd[i]);
}

__global__ __launch_bounds__(256) void wo_kernel(
    const float* __restrict__ emb, const float* __restrict__ op_emb,
    float* __restrict__ outp)
{
    __shared__ float ops[DD * 32];
    int tid = threadIdx.x;
    for (int i = tid; i < DD * 32; i += 256) {
        int d = i >> 5, o = i & 31;
        ops[d * 32 + o] = op_emb[o * DD + d];
    }
    __syncthreads();
    int r = tid >> 5, o = tid & 31;
    int gr = blockIdx.x * 8 + r;
    int b = gr >> 9, n = gr & 511;
    const float* erow = emb + (((size_t)n * BB) + b) * DD;
    float acc = 0.0f;
#pragma unroll 16
    for (int d = 0; d < DD; d++) acc += erow[d] * ops[d * 32 + o];
    outp[OFF_WO + (size_t)gr * 32 + o] = thresh_sigmoid(acc);
}

__global__ void pade_kernel(float* __restrict__ outp) {
    size_t i = (size_t)blockIdx.x * blockDim.x + threadIdx.x;
    if (i >= (size_t)SS * BB * HH) return;
    size_t s = i / (BB * HH);
    size_t r = i % (BB * HH);
    size_t b = r / HH, j = r % HH;
    size_t base = (s * BB + b) * (2 * HH);
    outp[OFF_PADE + i] = g_out1[base + j] + g_out1[base + HH + j];
}

__global__ void prob_kernel(float* __restrict__ outp) {
    int i = blockIdx.x * blockDim.x + threadIdx.x;
    if (i >= BB * HH) return;
    int b = i / HH, j = i % HH;
    outp[OFF_PROB + i] =
        g_out1[(((size_t)(SS - 1) * BB) + b) * (2 * HH) + j] +
        g_out1[((size_t)b) * (2 * HH) + HH + j];
}

// ---------------------------------------------------------------------------
extern "C" void kernel_launch(void* const* d_in, const int* in_sizes, int n_in,
                              void* d_out, int out_size)
{
    const float* emb    = (const float*)d_in[0];
    const float* op_emb = (const float*)d_in[2];
    const float* wih0f = (const float*)d_in[3],  *whh0f = (const float*)d_in[4];
    const float* bih0f = (const float*)d_in[5],  *bhh0f = (const float*)d_in[6];
    const float* wih0b = (const float*)d_in[7],  *whh0b = (const float*)d_in[8];
    const float* bih0b = (const float*)d_in[9],  *bhh0b = (const float*)d_in[10];
    const float* wih1f = (const float*)d_in[11], *whh1f = (const float*)d_in[12];
    const float* bih1f = (const float*)d_in[13], *bhh1f = (const float*)d_in[14];
    const float* wih1b = (const float*)d_in[15], *whh1b = (const float*)d_in[16];
    const float* bih1b = (const float*)d_in[17], *bhh1b = (const float*)d_in[18];
    float* outp = (float*)d_out;

    void *pPreF, *pPreB, *pOut0, *pOut1, *pH, *pCtr;
    cudaGetSymbolAddress(&pPreF, g_preF);
    cudaGetSymbolAddress(&pPreB, g_preB);
    cudaGetSymbolAddress(&pOut0, g_out0);
    cudaGetSymbolAddress(&pOut1, g_out1);
    cudaGetSymbolAddress(&pH,    g_h);
    cudaGetSymbolAddress(&pCtr,  g_ctr);
    float* preF = (float*)pPreF;  float* preB = (float*)pPreB;
    float* out0 = (float*)pOut0;  float* out1 = (float*)pOut1;
    float* hb   = (float*)pH;     unsigned* ctr = (unsigned*)pCtr;

    const int SMEM_LSTM =
        (2 * HH * BB + 4 * 32 * RED_STRIDE) * (int)sizeof(float);
    cudaFuncSetAttribute(lstm_kernel,
        cudaFuncAttributeMaxDynamicSharedMemorySize, SMEM_LSTM);

    init_kernel<<<512, 256>>>();

    dim3 ggrid(16, 128);
    gemm_pre_kernel<<<ggrid, 256>>>(emb, wih0f, bih0f, bhh0f, preF, DD, 0);
    gemm_pre_kernel<<<ggrid, 256>>>(emb, wih0b, bih0b, bhh0b, preB, DD, 1);
    lstm_kernel<<<128, 256, SMEM_LSTM>>>(preF, preB, whh0f, whh0b,
                                         out0, hb, ctr);
    gemm_pre_kernel<<<ggrid, 256>>>(out0, wih1f, bih1f, bhh1f, preF, 2 * HH, 0);
    gemm_pre_kernel<<<ggrid, 256>>>(out0, wih1b, bih1b, bhh1b, preB, 2 * HH, 1);
    lstm_kernel<<<128, 256, SMEM_LSTM>>>(preF, preB, whh1f, whh1b,
                                         out1, hb + 2 * 2 * HH * BB, ctr + 2);

    sq_kernel<<<(SS * BB * 32 + 255) / 256, 256>>>(emb);
    dim3 pgrid(8, 8, 32);
    pd_kernel<<<pgrid, 256>>>(emb);
    sum_reduce_kernel<<<1, 256>>>();
    ww_final_kernel<<<32768, 256>>>(outp);
    wo_kernel<<<2048, 256>>>(emb, op_emb, outp);
    pade_kernel<<<32768, 256>>>(outp);
    prob_kernel<<<64, 256>>>(outp);
}

// round 15
// speedup vs baseline: 1.5120x; 1.1211x over previous
#include <cuda_runtime.h>
#include <cuda_bf16.h>
#include <cstdint>
#include <math.h>

#define SS 512
#define BB 32
#define DD 128
#define HH 512
#define G4 2048
#define OFF_PADE 0u
#define OFF_PROB 8388608u
#define OFF_WW   8404992u
#define OFF_WO   16793600u

// ---------------- scratch ----------------
__device__ __align__(16) float g_preF[(size_t)SS * BB * G4];   // [s*32+b][n]
__device__ __align__(16) float g_preB[(size_t)SS * BB * G4];
__device__ __align__(16) float g_out0[(size_t)SS * BB * 2 * HH];
__device__ __align__(16) float g_out1[(size_t)SS * BB * 2 * HH];
__device__ __align__(16) float g_h[2 * 2 * 2 * HH * BB];
__device__ unsigned g_ctr[4];
__device__ float    g_sq[BB * SS];
__device__ __align__(16) float g_pd[(size_t)BB * SS * SS];
__device__ float    g_bsum[2048];
__device__ double   g_sum;
__device__ __align__(16) __nv_bfloat16 g_Ahi[(size_t)16384 * 1024];
__device__ __align__(16) __nv_bfloat16 g_Alo[(size_t)16384 * 1024];
__device__ __align__(16) __nv_bfloat16 g_Whi[(size_t)2048 * 1024];
__device__ __align__(16) __nv_bfloat16 g_Wlo[(size_t)2048 * 1024];

// ---------------- f32x2 helpers (LSTM) ----------------
__device__ __forceinline__ void fma2(unsigned long long& acc,
                                     unsigned long long a, unsigned long long b) {
    asm("fma.rn.f32x2 %0, %1, %2, %0;" : "+l"(acc) : "l"(a), "l"(b));
}
__device__ __forceinline__ unsigned long long p2(float x, float y) {
    unsigned long long r; asm("mov.b64 %0, {%1,%2};" : "=l"(r) : "f"(x), "f"(y)); return r;
}
__device__ __forceinline__ unsigned long long add2(unsigned long long a,
                                                   unsigned long long b) {
    unsigned long long r; asm("add.rn.f32x2 %0, %1, %2;" : "=l"(r) : "l"(a), "l"(b));
    return r;
}

__global__ void init_kernel() {
    int i = blockIdx.x * blockDim.x + threadIdx.x;
    if (i < 2 * 2 * 2 * HH * BB) g_h[i] = 0.0f;
    if (i < 4) g_ctr[i] = 0u;
    if (i == 0) g_sum = 0.0;
}

// ---------------- fp32 -> (bf16 hi, bf16 lo) split ----------------
__global__ void split_kernel(const float* __restrict__ x,
                             __nv_bfloat16* __restrict__ hi,
                             __nv_bfloat16* __restrict__ lo, int n) {
    int i = (blockIdx.x * blockDim.x + threadIdx.x) * 4;
    if (i >= n) return;
    float4 v = *reinterpret_cast<const float4*>(x + i);
    __nv_bfloat16 h0 = __float2bfloat16(v.x);
    __nv_bfloat16 h1 = __float2bfloat16(v.y);
    __nv_bfloat16 h2 = __float2bfloat16(v.z);
    __nv_bfloat16 h3 = __float2bfloat16(v.w);
    __nv_bfloat16 l0 = __float2bfloat16(v.x - __bfloat162float(h0));
    __nv_bfloat16 l1 = __float2bfloat16(v.y - __bfloat162float(h1));
    __nv_bfloat16 l2 = __float2bfloat16(v.z - __bfloat162float(h2));
    __nv_bfloat16 l3 = __float2bfloat16(v.w - __bfloat162float(h3));
    uint2 hp, lp;
    hp.x = ((uint32_t)__bfloat16_as_ushort(h1) << 16) | __bfloat16_as_ushort(h0);
    hp.y = ((uint32_t)__bfloat16_as_ushort(h3) << 16) | __bfloat16_as_ushort(h2);
    lp.x = ((uint32_t)__bfloat16_as_ushort(l1) << 16) | __bfloat16_as_ushort(l0);
    lp.y = ((uint32_t)__bfloat16_as_ushort(l3) << 16) | __bfloat16_as_ushort(l2);
    *reinterpret_cast<uint2*>(reinterpret_cast<char*>(hi) + (size_t)i * 2) = hp;
    *reinterpret_cast<uint2*>(reinterpret_cast<char*>(lo) + (size_t)i * 2) = lp;
}

// ---------------- mma.sync helpers ----------------
__device__ __forceinline__ uint32_t s2u(const void* p) {
    uint32_t a;
    asm("{ .reg .u64 t; cvta.to.shared.u64 t, %1; cvt.u32.u64 %0, t; }"
        : "=r"(a) : "l"(p));
    return a;
}
#define SWZ(x) ((x) ^ (((x) >> 3) & 0x70))

#define LDSM4(R, A) \
    asm volatile("ldmatrix.sync.aligned.m8n8.x4.shared.b16 {%0,%1,%2,%3}, [%4];" \
        : "=r"((R)[0]), "=r"((R)[1]), "=r"((R)[2]), "=r"((R)[3]) : "r"(A))

#define MMA(D, A, B0, B1) \
    asm volatile("mma.sync.aligned.m16n8k16.row.col.f32.bf16.bf16.f32 " \
        "{%0,%1,%2,%3}, {%4,%5,%6,%7}, {%8,%9}, {%0,%1,%2,%3};" \
        : "+f"((D)[0]), "+f"((D)[1]), "+f"((D)[2]), "+f"((D)[3]) \
        : "r"((A)[0]), "r"((A)[1]), "r"((A)[2]), "r"((A)[3]), "r"(B0), "r"(B1))

// ---- tensor-core projection GEMM with 3-product bf16 split ----
// C[m][n] = A[M,K] @ W[N,K]^T + bih[n] + bhh[n]; rev flips s in A rows
__global__ __launch_bounds__(256) void mma_pre_kernel(
    const __nv_bfloat16* __restrict__ Ahi, const __nv_bfloat16* __restrict__ Alo,
    const __nv_bfloat16* __restrict__ Whi, const __nv_bfloat16* __restrict__ Wlo,
    const float* __restrict__ bih, const float* __restrict__ bhh,
    float* __restrict__ C, int K, int rev)
{
    extern __shared__ char dsm[];
    uint32_t raw  = s2u(dsm);
    uint32_t base = (raw + 1023u) & ~1023u;
    char* sm = dsm + (base - raw);

    const int tid  = threadIdx.x;
    const int wid  = tid >> 5;
    const int lane = tid & 31;
    const int n0 = blockIdx.x * 128;
    const int m0 = blockIdx.y * 128;
    const int wm = (wid >> 1) * 32;
    const int wn = (wid & 1) * 64;

    float acc[2][8][4];
#pragma unroll
    for (int mt = 0; mt < 2; mt++)
#pragma unroll
        for (int nt = 0; nt < 8; nt++)
#pragma unroll
            for (int q = 0; q < 4; q++) acc[mt][nt][q] = 0.0f;

    const uint32_t bAhi = base, bAlo = base + 16384;
    const uint32_t bWhi = base + 32768, bWlo = base + 49152;

    // ldmatrix per-thread address components (SW128: swizzle bits come from row)
    uint32_t aoff[2], axr[2];
#pragma unroll
    for (int mt = 0; mt < 2; mt++) {
        uint32_t rb = (uint32_t)(wm + mt * 16 + (lane & 15)) * 128u;
        aoff[mt] = rb; axr[mt] = (rb >> 3) & 0x70u;
    }
    const uint32_t akh = (uint32_t)(lane >> 4) * 16u;
    uint32_t boff[4], bxr[4];
    {
        uint32_t bn = (uint32_t)(wn + (lane & 7) + ((lane >> 4) << 3));
#pragma unroll
        for (int np = 0; np < 4; np++) {
            uint32_t rb = (bn + np * 16) * 128u;
            boff[np] = rb; bxr[np] = (rb >> 3) & 0x70u;
        }
    }
    const uint32_t bkh = (uint32_t)((lane >> 3) & 1) * 16u;

    const int nchunks = K >> 6;
    for (int t = 0; t < nchunks; t++) {
        int kc = t << 6;
#pragma unroll
        for (int j = 0; j < 16; j++) {
            int u = tid + j * 256;
            int tile = u >> 10;
            int v = u & 1023;
            int row = v >> 3;
            int cb = (v & 7) * 8;
            const __nv_bfloat16* src;
            if (tile <= 1) {
                int rg = m0 + row;
                if (rev) rg = ((SS - 1 - (rg >> 5)) << 5) + (rg & 31);
                src = (tile == 0 ? Ahi : Alo) + (size_t)rg * K + kc + cb;
            } else {
                src = (tile == 2 ? Whi : Wlo) + (size_t)(n0 + row) * K + kc + cb;
            }
            uint4 val = *reinterpret_cast<const uint4*>(src);
            *reinterpret_cast<uint4*>(sm + tile * 16384 + SWZ(v * 16)) = val;
        }
        __syncthreads();
#pragma unroll
        for (int ks = 0; ks < 4; ks++) {
            uint32_t ko = (uint32_t)ks * 32u;
            uint32_t ah[2][4], al[2][4];
#pragma unroll
            for (int mt = 0; mt < 2; mt++) {
                LDSM4(ah[mt], bAhi + aoff[mt] + ((ko + akh) ^ axr[mt]));
                LDSM4(al[mt], bAlo + aoff[mt] + ((ko + akh) ^ axr[mt]));
            }
#pragma unroll
            for (int np = 0; np < 4; np++) {
                uint32_t bh[4], bl[4];
                LDSM4(bh, bWhi + boff[np] + ((ko + bkh) ^ bxr[np]));
                LDSM4(bl, bWlo + boff[np] + ((ko + bkh) ^ bxr[np]));
#pragma unroll
                for (int mt = 0; mt < 2; mt++)
#pragma unroll
                    for (int t2 = 0; t2 < 2; t2++) {
                        int nt = np * 2 + t2;
                        MMA(acc[mt][nt], ah[mt], bh[t2 * 2], bh[t2 * 2 + 1]);
                        MMA(acc[mt][nt], ah[mt], bl[t2 * 2], bl[t2 * 2 + 1]);
                        MMA(acc[mt][nt], al[mt], bh[t2 * 2], bh[t2 * 2 + 1]);
                    }
            }
        }
        __syncthreads();
    }

    // stage accumulators through smem (stride 132 -> aligned float4 rows)
    float* stage = reinterpret_cast<float*>(sm);
#pragma unroll
    for (int mt = 0; mt < 2; mt++)
#pragma unroll
        for (int nt = 0; nt < 8; nt++) {
            int r0 = wm + mt * 16 + (lane >> 2);
            int cc = wn + nt * 8 + (lane & 3) * 2;
            stage[r0 * 132 + cc]           = acc[mt][nt][0];
            stage[r0 * 132 + cc + 1]       = acc[mt][nt][1];
            stage[(r0 + 8) * 132 + cc]     = acc[mt][nt][2];
            stage[(r0 + 8) * 132 + cc + 1] = acc[mt][nt][3];
        }
    __syncthreads();

    int c4 = (tid & 31) * 4;
    float4 bias;
    bias.x = bih[n0 + c4]     + bhh[n0 + c4];
    bias.y = bih[n0 + c4 + 1] + bhh[n0 + c4 + 1];
    bias.z = bih[n0 + c4 + 2] + bhh[n0 + c4 + 2];
    bias.w = bih[n0 + c4 + 3] + bhh[n0 + c4 + 3];
    for (int r = tid >> 5; r < 128; r += 8) {
        float4 v = *reinterpret_cast<const float4*>(&stage[r * 132 + c4]);
        v.x += bias.x; v.y += bias.y; v.z += bias.z; v.w += bias.w;
        *reinterpret_cast<float4*>(&C[(size_t)(m0 + r) * G4 + n0 + c4]) = v;
    }
}

// ---------------- persistent bidirectional LSTM (R13, proven) ----------------
__device__ __forceinline__ float sigf(float x) { return 1.0f / (1.0f + expf(-x)); }

#define RED_STRIDE 34

__global__ __launch_bounds__(256) void lstm_kernel(
    const float* __restrict__ preF, const float* __restrict__ preB,
    const float* __restrict__ whhF, const float* __restrict__ whhB,
    float* __restrict__ out, float* __restrict__ hbase,
    unsigned* __restrict__ ctr)
{
    extern __shared__ float smf[];
    float* ws  = smf;
    float* hs  = smf + HH * BB;
    float* red = smf + 2 * HH * BB;

    const int tid = threadIdx.x;
    const int dir = blockIdx.x >> 6;
    const int blk = blockIdx.x & 63;
    const int j0  = blk * 8;

    const float* pre = dir ? preB : preF;
    const float* whh = dir ? whhB : whhF;
    float* hb = hbase + dir * (2 * HH * BB);
    unsigned* myctr = ctr + dir;

    for (int i = tid; i < HH * 32; i += 256) {
        int c = i >> 9;
        int k = i & 511;
        int ng = (c >> 3) * HH + j0 + (c & 7);
        ws[k * 32 + c] = whh[(size_t)ng * HH + k];
    }

    const int kg  = tid >> 6;
    const int t64 = tid & 63;
    const int tb  = (t64 & 7) * 4;
    const int tc  = (t64 >> 3) * 4;
    const int kbeg = kg * 128;
    const int ngb  = (tc >> 3) * HH + j0 + (tc & 7);

    const int uj = tid >> 5;
    const int ub = tid & 31;
    float c_reg = 0.0f;
    __syncthreads();

    for (int s = 0; s < SS; s++) {
        const float* hsrc = hb + (s & 1) * (HH * BB);
        float*       hdst = hb + ((s + 1) & 1) * (HH * BB);

        for (int i = tid * 4; i < HH * BB; i += 1024) {
            float4 v = __ldcg(reinterpret_cast<const float4*>(&hsrc[i]));
            *reinterpret_cast<float4*>(&hs[i]) = v;
        }
        float4 pv0 = make_float4(0.f,0.f,0.f,0.f), pv1 = pv0, pv2 = pv0, pv3 = pv0;
        if (kg == 0) {
            const float* pb = pre + (size_t)s * (BB * G4) + ngb;
            pv0 = __ldcg(reinterpret_cast<const float4*>(pb + (size_t)(tb + 0) * G4));
            pv1 = __ldcg(reinterpret_cast<const float4*>(pb + (size_t)(tb + 1) * G4));
            pv2 = __ldcg(reinterpret_cast<const float4*>(pb + (size_t)(tb + 2) * G4));
            pv3 = __ldcg(reinterpret_cast<const float4*>(pb + (size_t)(tb + 3) * G4));
        }
        __syncthreads();

        unsigned long long acc[4][2];
#pragma unroll
        for (int b = 0; b < 4; b++) { acc[b][0] = 0ull; acc[b][1] = 0ull; }

        const float* hp = hs + kbeg * 32 + tb;
        const float* wp = ws + kbeg * 32 + tc;
#pragma unroll 8
        for (int k = 0; k < 128; k++) {
            float4 h4 = *reinterpret_cast<const float4*>(hp);
            ulonglong2 w2 = *reinterpret_cast<const ulonglong2*>(wp);
            unsigned long long hd;
            hd = p2(h4.x, h4.x); fma2(acc[0][0], hd, w2.x); fma2(acc[0][1], hd, w2.y);
            hd = p2(h4.y, h4.y); fma2(acc[1][0], hd, w2.x); fma2(acc[1][1], hd, w2.y);
            hd = p2(h4.z, h4.z); fma2(acc[2][0], hd, w2.x); fma2(acc[2][1], hd, w2.y);
            hd = p2(h4.w, h4.w); fma2(acc[3][0], hd, w2.x); fma2(acc[3][1], hd, w2.y);
            hp += 32; wp += 32;
        }
        if (kg == 0) {
            acc[0][0] = add2(acc[0][0], p2(pv0.x, pv0.y));
            acc[0][1] = add2(acc[0][1], p2(pv0.z, pv0.w));
            acc[1][0] = add2(acc[1][0], p2(pv1.x, pv1.y));
            acc[1][1] = add2(acc[1][1], p2(pv1.z, pv1.w));
            acc[2][0] = add2(acc[2][0], p2(pv2.x, pv2.y));
            acc[2][1] = add2(acc[2][1], p2(pv2.z, pv2.w));
            acc[3][0] = add2(acc[3][0], p2(pv3.x, pv3.y));
            acc[3][1] = add2(acc[3][1], p2(pv3.z, pv3.w));
        }
#pragma unroll
        for (int b = 0; b < 4; b++) {
            unsigned long long* rp = reinterpret_cast<unsigned long long*>(
                &red[(kg * 32 + tb + b) * RED_STRIDE + tc]);
            rp[0] = acc[b][0];
            rp[1] = acc[b][1];
        }
        __syncthreads();

        float gv[4];
#pragma unroll
        for (int g = 0; g < 4; g++) {
            int c = g * 8 + uj;
            gv[g] = (red[(0 * 32 + ub) * RED_STRIDE + c] +
                     red[(1 * 32 + ub) * RED_STRIDE + c]) +
                    (red[(2 * 32 + ub) * RED_STRIDE + c] +
                     red[(3 * 32 + ub) * RED_STRIDE + c]);
        }
        c_reg = sigf(gv[1]) * c_reg + sigf(gv[0]) * tanhf(gv[2]);
        float hv = sigf(gv[3]) * tanhf(c_reg);

        __stcg(&hdst[(j0 + uj) * 32 + ub], hv);
        int so = dir ? (SS - 1 - s) : s;
        __stcg(&out[((size_t)so * BB + ub) * (2 * HH) + dir * HH + j0 + uj], hv);

        __syncthreads();
        if (tid == 0) {
            __threadfence();
            atomicAdd(myctr, 1u);
            unsigned target = 64u * (unsigned)(s + 1);
            while (*((volatile unsigned*)myctr) < target) { __nanosleep(32); }
            __threadfence();
        }
        __syncthreads();
    }
}

// ---------------- sq ----------------
__global__ void sq_kernel(const float* __restrict__ emb) {
    int gwarp = (blockIdx.x * blockDim.x + threadIdx.x) >> 5;
    int lane  = threadIdx.x & 31;
    if (gwarp >= SS * BB) return;
    const float* rowp = emb + (size_t)gwarp * DD;
    float ssum = 0.0f;
#pragma unroll
    for (int d = lane; d < DD; d += 32) { float v = rowp[d]; ssum += v * v; }
#pragma unroll
    for (int o = 16; o > 0; o >>= 1) ssum += __shfl_down_sync(0xffffffffu, ssum, o);
    if (lane == 0) {
        int s = gwarp >> 5, b = gwarp & 31;
        g_sq[b * SS + s] = ssum;
    }
}

// ---------------- pd + block sums ----------------
__global__ __launch_bounds__(256) void pd_kernel(const float* __restrict__ emb) {
    __shared__ __align__(16) float Ans[64][68];
    __shared__ __align__(16) float Ams[64][68];
    __shared__ float redsm[256];
    const int b  = blockIdx.z;
    const int n0 = blockIdx.y * 64;
    const int m0 = blockIdx.x * 64;
    const int tid = threadIdx.x;
    const int tx = tid & 15, ty = tid >> 4;

    float acc[4][4];
#pragma unroll
    for (int i = 0; i < 4; i++)
#pragma unroll
        for (int j = 0; j < 4; j++) acc[i][j] = 0.0f;

    for (int kc = 0; kc < DD; kc += 64) {
#pragma unroll
        for (int r = 0; r < 4; r++) {
            int idx = tid + r * 256;
            int row = idx >> 4;
            int kf  = (idx & 15) * 4;
            float4 vn = *reinterpret_cast<const float4*>(
                &emb[(((size_t)(n0 + row)) * BB + b) * DD + kc + kf]);
            Ans[kf + 0][row] = vn.x; Ans[kf + 1][row] = vn.y;
            Ans[kf + 2][row] = vn.z; Ans[kf + 3][row] = vn.w;
            float4 vm = *reinterpret_cast<const float4*>(
                &emb[(((size_t)(m0 + row)) * BB + b) * DD + kc + kf]);
            Ams[kf + 0][row] = vm.x; Ams[kf + 1][row] = vm.y;
            Ams[kf + 2][row] = vm.z; Ams[kf + 3][row] = vm.w;
        }
        __syncthreads();
#pragma unroll 8
        for (int kk = 0; kk < 64; kk++) {
            float4 an = *reinterpret_cast<const float4*>(&Ans[kk][ty * 4]);
            float4 am = *reinterpret_cast<const float4*>(&Ams[kk][tx * 4]);
            float av[4] = {an.x, an.y, an.z, an.w};
            float bv[4] = {am.x, am.y, am.z, am.w};
#pragma unroll
            for (int i = 0; i < 4; i++)
#pragma unroll
                for (int j = 0; j < 4; j++) acc[i][j] += av[i] * bv[j];
        }
        __syncthreads();
    }

    float sqn[4], sqm[4];
#pragma unroll
    for (int i = 0; i < 4; i++) sqn[i] = g_sq[b * SS + n0 + ty * 4 + i];
#pragma unroll
    for (int j = 0; j < 4; j++) sqm[j] = g_sq[b * SS + m0 + tx * 4 + j];

    float lsum = 0.0f;
#pragma unroll
    for (int i = 0; i < 4; i++) {
        int n = n0 + ty * 4 + i;
        float* prow = g_pd + (((size_t)b * SS) + n) * SS + m0 + tx * 4;
        float4 v;
        float* vp = &v.x;
#pragma unroll
        for (int j = 0; j < 4; j++) {
            float d2 = fmaxf(sqn[i] + sqm[j] - 2.0f * acc[i][j], 0.0f);
            float pdv = (d2 > 0.0f) ? sqrtf(d2) : 0.0f;
            vp[j] = pdv;
            lsum += pdv;
        }
        *reinterpret_cast<float4*>(prow) = v;
    }

    redsm[tid] = lsum;
    __syncthreads();
    for (int o = 128; o > 0; o >>= 1) {
        if (tid < o) redsm[tid] += redsm[tid + o];
        __syncthreads();
    }
    if (tid == 0)
        g_bsum[blockIdx.z * 64 + blockIdx.y * 8 + blockIdx.x] = redsm[0];
}

__global__ void sum_reduce_kernel() {
    __shared__ double red[256];
    int tid = threadIdx.x;
    double s = 0.0;
    for (int i = tid; i < 2048; i += 256) s += (double)g_bsum[i];
    red[tid] = s;
    __syncthreads();
    for (int o = 128; o > 0; o >>= 1) {
        if (tid < o) red[tid] += red[tid + o];
        __syncthreads();
    }
    if (tid == 0) g_sum = red[0];
}

__device__ __forceinline__ float thresh_sigmoid(float dis) {
    if (dis < -1e-3f) return 0.0f;
    if (dis > 1e-3f)  return 1.0f / (1.0f + __expf(-dis));
    float sv = 1.0f / (1.0f + expf(-dis));
    return (sv < 0.5f) ? 0.0f : sv;
}

__global__ void ww_final_kernel(float* __restrict__ outp) {
    size_t i = (size_t)blockIdx.x * blockDim.x + threadIdx.x;
    if (i >= (size_t)BB * SS * SS) return;
    float mean = (float)(g_sum / (double)((size_t)BB * SS * SS));
    outp[OFF_WW + i] = thresh_sigmoid(mean - g_pd[i]);
}

__global__ __launch_bounds__(256) void wo_kernel(
    const float* __restrict__ emb, const float* __restrict__ op_emb,
    float* __restrict__ outp)
{
    __shared__ float ops[DD * 32];
    int tid = threadIdx.x;
    for (int i = tid; i < DD * 32; i += 256) {
        int d = i >> 5, o = i & 31;
        ops[d * 32 + o] = op_emb[o * DD + d];
    }
    __syncthreads();
    int r = tid >> 5, o = tid & 31;
    int gr = blockIdx.x * 8 + r;
    int b = gr >> 9, n = gr & 511;
    const float* erow = emb + (((size_t)n * BB) + b) * DD;
    float acc = 0.0f;
#pragma unroll 16
    for (int d = 0; d < DD; d++) acc += erow[d] * ops[d * 32 + o];
    outp[OFF_WO + (size_t)gr * 32 + o] = thresh_sigmoid(acc);
}

__global__ void pade_kernel(float* __restrict__ outp) {
    size_t i = (size_t)blockIdx.x * blockDim.x + threadIdx.x;
    if (i >= (size_t)SS * BB * HH) return;
    size_t s = i / (BB * HH);
    size_t r = i % (BB * HH);
    size_t b = r / HH, j = r % HH;
    size_t base = (s * BB + b) * (2 * HH);
    outp[OFF_PADE + i] = g_out1[base + j] + g_out1[base + HH + j];
}

__global__ void prob_kernel(float* __restrict__ outp) {
    int i = blockIdx.x * blockDim.x + threadIdx.x;
    if (i >= BB * HH) return;
    int b = i / HH, j = i % HH;
    outp[OFF_PROB + i] =
        g_out1[(((size_t)(SS - 1) * BB) + b) * (2 * HH) + j] +
        g_out1[((size_t)b) * (2 * HH) + HH + j];
}

// ---------------------------------------------------------------------------
extern "C" void kernel_launch(void* const* d_in, const int* in_sizes, int n_in,
                              void* d_out, int out_size)
{
    const float* emb    = (const float*)d_in[0];
    const float* op_emb = (const float*)d_in[2];
    const float* wih0f = (const float*)d_in[3],  *whh0f = (const float*)d_in[4];
    const float* bih0f = (const float*)d_in[5],  *bhh0f = (const float*)d_in[6];
    const float* wih0b = (const float*)d_in[7],  *whh0b = (const float*)d_in[8];
    const float* bih0b = (const float*)d_in[9],  *bhh0b = (const float*)d_in[10];
    const float* wih1f = (const float*)d_in[11], *whh1f = (const float*)d_in[12];
    const float* bih1f = (const float*)d_in[13], *bhh1f = (const float*)d_in[14];
    const float* wih1b = (const float*)d_in[15], *whh1b = (const float*)d_in[16];
    const float* bih1b = (const float*)d_in[17], *bhh1b = (const float*)d_in[18];
    float* outp = (float*)d_out;

    void *pPreF, *pPreB, *pOut0, *pOut1, *pH, *pCtr;
    void *pAhi, *pAlo, *pWhi, *pWlo;
    cudaGetSymbolAddress(&pPreF, g_preF);
    cudaGetSymbolAddress(&pPreB, g_preB);
    cudaGetSymbolAddress(&pOut0, g_out0);
    cudaGetSymbolAddress(&pOut1, g_out1);
    cudaGetSymbolAddress(&pH,    g_h);
    cudaGetSymbolAddress(&pCtr,  g_ctr);
    cudaGetSymbolAddress(&pAhi,  g_Ahi);
    cudaGetSymbolAddress(&pAlo,  g_Alo);
    cudaGetSymbolAddress(&pWhi,  g_Whi);
    cudaGetSymbolAddress(&pWlo,  g_Wlo);
    float* preF = (float*)pPreF;  float* preB = (float*)pPreB;
    float* out0 = (float*)pOut0;  float* out1 = (float*)pOut1;
    float* hb   = (float*)pH;     unsigned* ctr = (unsigned*)pCtr;
    __nv_bfloat16* Ahi = (__nv_bfloat16*)pAhi;
    __nv_bfloat16* Alo = (__nv_bfloat16*)pAlo;
    __nv_bfloat16* Whi = (__nv_bfloat16*)pWhi;
    __nv_bfloat16* Wlo = (__nv_bfloat16*)pWlo;

    const int SMEM_LSTM =
        (2 * HH * BB + 4 * 32 * RED_STRIDE) * (int)sizeof(float);
    cudaFuncSetAttribute(lstm_kernel,
        cudaFuncAttributeMaxDynamicSharedMemorySize, SMEM_LSTM);
    const int SMEM_MMA = 1024 + 128 * 132 * 4;   // align slack + stage (>= operands)
    cudaFuncSetAttribute(mma_pre_kernel,
        cudaFuncAttributeMaxDynamicSharedMemorySize, SMEM_MMA);

    init_kernel<<<512, 256>>>();

    dim3 ggrid(16, 128);
    // ---- layer 0 (K = 128) ----
    split_kernel<<<16384 * 128 / 1024, 256>>>(emb, Ahi, Alo, 16384 * 128);
    split_kernel<<<2048 * 128 / 1024, 256>>>(wih0f, Whi, Wlo, 2048 * 128);
    mma_pre_kernel<<<ggrid, 256, SMEM_MMA>>>(Ahi, Alo, Whi, Wlo,
                                             bih0f, bhh0f, preF, 128, 0);
    split_kernel<<<2048 * 128 / 1024, 256>>>(wih0b, Whi, Wlo, 2048 * 128);
    mma_pre_kernel<<<ggrid, 256, SMEM_MMA>>>(Ahi, Alo, Whi, Wlo,
                                             bih0b, bhh0b, preB, 128, 1);
    lstm_kernel<<<128, 256, SMEM_LSTM>>>(preF, preB, whh0f, whh0b,
                                         out0, hb, ctr);
    // ---- layer 1 (K = 1024) ----
    split_kernel<<<16384 * 1024 / 1024, 256>>>(out0, Ahi, Alo, 16384 * 1024);
    split_kernel<<<2048 * 1024 / 1024, 256>>>(wih1f, Whi, Wlo, 2048 * 1024);
    mma_pre_kernel<<<ggrid, 256, SMEM_MMA>>>(Ahi, Alo, Whi, Wlo,
                                             bih1f, bhh1f, preF, 1024, 0);
    split_kernel<<<2048 * 1024 / 1024, 256>>>(wih1b, Whi, Wlo, 2048 * 1024);
    mma_pre_kernel<<<ggrid, 256, SMEM_MMA>>>(Ahi, Alo, Whi, Wlo,
                                             bih1b, bhh1b, preB, 1024, 1);
    lstm_kernel<<<128, 256, SMEM_LSTM>>>(preF, preB, whh1f, whh1b,
                                         out1, hb + 2 * 2 * HH * BB, ctr + 2);

    // ---- tails ----
    sq_kernel<<<(SS * BB * 32 + 255) / 256, 256>>>(emb);
    dim3 pgrid(8, 8, 32);
    pd_kernel<<<pgrid, 256>>>(emb);
    sum_reduce_kernel<<<1, 256>>>();
    ww_final_kernel<<<32768, 256>>>(outp);
    wo_kernel<<<2048, 256>>>(emb, op_emb, outp);
    pade_kernel<<<32768, 256>>>(outp);
    prob_kernel<<<64, 256>>>(outp);
}

// round 16
// speedup vs baseline: 1.6547x; 1.0944x over previous
#include <cuda_runtime.h>
#include <cuda_bf16.h>
#include <cstdint>
#include <math.h>

#define SS 512
#define BB 32
#define DD 128
#define HH 512
#define G4 2048
#define OFF_PADE 0u
#define OFF_PROB 8388608u
#define OFF_WW   8404992u
#define OFF_WO   16793600u

// ---------------- scratch ----------------
__device__ __align__(16) float g_preF[(size_t)SS * BB * G4];   // [s*32+b][n]
__device__ __align__(16) float g_preB[(size_t)SS * BB * G4];
__device__ __align__(16) float g_out0[(size_t)SS * BB * 2 * HH];
__device__ __align__(16) float g_out1[(size_t)SS * BB * 2 * HH];
__device__ __align__(16) float g_h[2 * 2 * 2 * HH * BB];
__device__ unsigned g_ctr[4];
__device__ float    g_sq[BB * SS];
__device__ __align__(16) float g_pd[(size_t)BB * SS * SS];
__device__ float    g_bsum[2048];
__device__ double   g_sum;
__device__ __align__(16) __nv_bfloat16 g_Ahi[(size_t)16384 * 1024];
__device__ __align__(16) __nv_bfloat16 g_Alo[(size_t)16384 * 1024];
__device__ __align__(16) __nv_bfloat16 g_Whi[(size_t)2048 * 1024];
__device__ __align__(16) __nv_bfloat16 g_Wlo[(size_t)2048 * 1024];

// ---------------- f32x2 helpers (LSTM) ----------------
__device__ __forceinline__ void fma2(unsigned long long& acc,
                                     unsigned long long a, unsigned long long b) {
    asm("fma.rn.f32x2 %0, %1, %2, %0;" : "+l"(acc) : "l"(a), "l"(b));
}
__device__ __forceinline__ unsigned long long p2(float x, float y) {
    unsigned long long r; asm("mov.b64 %0, {%1,%2};" : "=l"(r) : "f"(x), "f"(y)); return r;
}
__device__ __forceinline__ unsigned long long add2(unsigned long long a,
                                                   unsigned long long b) {
    unsigned long long r; asm("add.rn.f32x2 %0, %1, %2;" : "=l"(r) : "l"(a), "l"(b));
    return r;
}

__global__ void init_kernel() {
    int i = blockIdx.x * blockDim.x + threadIdx.x;
    if (i < 2 * 2 * 2 * HH * BB) g_h[i] = 0.0f;
    if (i < 4) g_ctr[i] = 0u;
    if (i == 0) g_sum = 0.0;
}

// ---------------- fp32 -> (bf16 hi, bf16 lo) split ----------------
__global__ void split_kernel(const float* __restrict__ x,
                             __nv_bfloat16* __restrict__ hi,
                             __nv_bfloat16* __restrict__ lo, int n) {
    int i = (blockIdx.x * blockDim.x + threadIdx.x) * 4;
    if (i >= n) return;
    float4 v = *reinterpret_cast<const float4*>(x + i);
    __nv_bfloat16 h0 = __float2bfloat16(v.x);
    __nv_bfloat16 h1 = __float2bfloat16(v.y);
    __nv_bfloat16 h2 = __float2bfloat16(v.z);
    __nv_bfloat16 h3 = __float2bfloat16(v.w);
    __nv_bfloat16 l0 = __float2bfloat16(v.x - __bfloat162float(h0));
    __nv_bfloat16 l1 = __float2bfloat16(v.y - __bfloat162float(h1));
    __nv_bfloat16 l2 = __float2bfloat16(v.z - __bfloat162float(h2));
    __nv_bfloat16 l3 = __float2bfloat16(v.w - __bfloat162float(h3));
    uint2 hp, lp;
    hp.x = ((uint32_t)__bfloat16_as_ushort(h1) << 16) | __bfloat16_as_ushort(h0);
    hp.y = ((uint32_t)__bfloat16_as_ushort(h3) << 16) | __bfloat16_as_ushort(h2);
    lp.x = ((uint32_t)__bfloat16_as_ushort(l1) << 16) | __bfloat16_as_ushort(l0);
    lp.y = ((uint32_t)__bfloat16_as_ushort(l3) << 16) | __bfloat16_as_ushort(l2);
    *reinterpret_cast<uint2*>(reinterpret_cast<char*>(hi) + (size_t)i * 2) = hp;
    *reinterpret_cast<uint2*>(reinterpret_cast<char*>(lo) + (size_t)i * 2) = lp;
}

// ---------------- mma.sync helpers ----------------
__device__ __forceinline__ uint32_t s2u(const void* p) {
    uint32_t a;
    asm("{ .reg .u64 t; cvta.to.shared.u64 t, %1; cvt.u32.u64 %0, t; }"
        : "=r"(a) : "l"(p));
    return a;
}
#define SWZ(x) ((x) ^ (((x) >> 3) & 0x70))

#define LDSM4(R, A) \
    asm volatile("ldmatrix.sync.aligned.m8n8.x4.shared.b16 {%0,%1,%2,%3}, [%4];" \
        : "=r"((R)[0]), "=r"((R)[1]), "=r"((R)[2]), "=r"((R)[3]) : "r"(A))

#define MMA(D, A, B0, B1) \
    asm volatile("mma.sync.aligned.m16n8k16.row.col.f32.bf16.bf16.f32 " \
        "{%0,%1,%2,%3}, {%4,%5,%6,%7}, {%8,%9}, {%0,%1,%2,%3};" \
        : "+f"((D)[0]), "+f"((D)[1]), "+f"((D)[2]), "+f"((D)[3]) \
        : "r"((A)[0]), "r"((A)[1]), "r"((A)[2]), "r"((A)[3]), "r"(B0), "r"(B1))

#define CP16(dst, src) \
    asm volatile("cp.async.cg.shared.global [%0], [%1], 16;" \
        :: "r"(dst), "l"(src) : "memory")
#define CPCOMMIT() asm volatile("cp.async.commit_group;" ::: "memory")
#define CPWAIT1()  asm volatile("cp.async.wait_group 1;" ::: "memory")
#define CPWAIT0()  asm volatile("cp.async.wait_group 0;" ::: "memory")

// ---- tensor-core projection GEMM, 3-product bf16 split, cp.async 2-stage ----
// C[m][n] = A[M,K] @ W[N,K]^T + bih[n] + bhh[n]; rev flips s in A rows
__global__ __launch_bounds__(256) void mma_pre_kernel(
    const __nv_bfloat16* __restrict__ Ahi, const __nv_bfloat16* __restrict__ Alo,
    const __nv_bfloat16* __restrict__ Whi, const __nv_bfloat16* __restrict__ Wlo,
    const float* __restrict__ bih, const float* __restrict__ bhh,
    float* __restrict__ C, int K, int rev)
{
    extern __shared__ char dsm[];
    uint32_t raw  = s2u(dsm);
    uint32_t base = (raw + 1023u) & ~1023u;
    char* sm = dsm + (base - raw);

    const int tid  = threadIdx.x;
    const int wid  = tid >> 5;
    const int lane = tid & 31;
    const int n0 = blockIdx.x * 128;
    const int m0 = blockIdx.y * 128;
    const int wm = (wid >> 1) * 32;
    const int wn = (wid & 1) * 64;

    float acc[2][8][4];
#pragma unroll
    for (int mt = 0; mt < 2; mt++)
#pragma unroll
        for (int nt = 0; nt < 8; nt++)
#pragma unroll
            for (int q = 0; q < 4; q++) acc[mt][nt][q] = 0.0f;

    // per-thread source mapping for chunk loads (fixed across chunks)
    const int tileId = tid >> 6;          // 0..3 : Ahi,Alo,Whi,Wlo  (j adds 4 per pass)
    // but original mapping iterates j over 16: u = tid + j*256; tile = u>>10
    // keep identical mapping, just via cp.async.

    uint32_t aoff[2], axr[2];
#pragma unroll
    for (int mt = 0; mt < 2; mt++) {
        uint32_t rb = (uint32_t)(wm + mt * 16 + (lane & 15)) * 128u;
        aoff[mt] = rb; axr[mt] = (rb >> 3) & 0x70u;
    }
    const uint32_t akh = (uint32_t)(lane >> 4) * 16u;
    uint32_t boff[4], bxr[4];
    {
        uint32_t bn = (uint32_t)(wn + (lane & 7) + ((lane >> 4) << 3));
#pragma unroll
        for (int np = 0; np < 4; np++) {
            uint32_t rb = (bn + np * 16) * 128u;
            boff[np] = rb; bxr[np] = (rb >> 3) & 0x70u;
        }
    }
    const uint32_t bkh = (uint32_t)((lane >> 3) & 1) * 16u;
    (void)tileId;

    const int nchunks = K >> 6;

    // issue one 64KB chunk into buffer `buf` via cp.async
    auto issue_chunk = [&](int t, int buf) {
        int kc = t << 6;
        uint32_t dbase = base + (uint32_t)buf * 65536u;
#pragma unroll
        for (int j = 0; j < 16; j++) {
            int u = tid + j * 256;
            int tile = u >> 10;
            int v = u & 1023;
            int row = v >> 3;
            int cb = (v & 7) * 8;
            const __nv_bfloat16* src;
            if (tile <= 1) {
                int rg = m0 + row;
                if (rev) rg = ((SS - 1 - (rg >> 5)) << 5) + (rg & 31);
                src = (tile == 0 ? Ahi : Alo) + (size_t)rg * K + kc + cb;
            } else {
                src = (tile == 2 ? Whi : Wlo) + (size_t)(n0 + row) * K + kc + cb;
            }
            CP16(dbase + (uint32_t)(tile * 16384 + SWZ(v * 16)), src);
        }
        CPCOMMIT();
    };

    issue_chunk(0, 0);
    for (int t = 0; t < nchunks; t++) {
        if (t + 1 < nchunks) {
            issue_chunk(t + 1, (t + 1) & 1);
            CPWAIT1();
        } else {
            CPWAIT0();
        }
        __syncthreads();
        uint32_t bufb = base + (uint32_t)(t & 1) * 65536u;
        uint32_t bAhi = bufb, bAlo = bufb + 16384;
        uint32_t bWhi = bufb + 32768, bWlo = bufb + 49152;
#pragma unroll
        for (int ks = 0; ks < 4; ks++) {
            uint32_t ko = (uint32_t)ks * 32u;
            uint32_t ah[2][4], al[2][4];
#pragma unroll
            for (int mt = 0; mt < 2; mt++) {
                LDSM4(ah[mt], bAhi + aoff[mt] + ((ko + akh) ^ axr[mt]));
                LDSM4(al[mt], bAlo + aoff[mt] + ((ko + akh) ^ axr[mt]));
            }
#pragma unroll
            for (int np = 0; np < 4; np++) {
                uint32_t bh[4], bl[4];
                LDSM4(bh, bWhi + boff[np] + ((ko + bkh) ^ bxr[np]));
                LDSM4(bl, bWlo + boff[np] + ((ko + bkh) ^ bxr[np]));
#pragma unroll
                for (int mt = 0; mt < 2; mt++)
#pragma unroll
                    for (int t2 = 0; t2 < 2; t2++) {
                        int nt = np * 2 + t2;
                        MMA(acc[mt][nt], ah[mt], bh[t2 * 2], bh[t2 * 2 + 1]);
                        MMA(acc[mt][nt], ah[mt], bl[t2 * 2], bl[t2 * 2 + 1]);
                        MMA(acc[mt][nt], al[mt], bh[t2 * 2], bh[t2 * 2 + 1]);
                    }
            }
        }
        __syncthreads();
    }

    // stage accumulators through smem (stride 132 -> aligned float4 rows)
    float* stage = reinterpret_cast<float*>(sm);
#pragma unroll
    for (int mt = 0; mt < 2; mt++)
#pragma unroll
        for (int nt = 0; nt < 8; nt++) {
            int r0 = wm + mt * 16 + (lane >> 2);
            int cc = wn + nt * 8 + (lane & 3) * 2;
            stage[r0 * 132 + cc]           = acc[mt][nt][0];
            stage[r0 * 132 + cc + 1]       = acc[mt][nt][1];
            stage[(r0 + 8) * 132 + cc]     = acc[mt][nt][2];
            stage[(r0 + 8) * 132 + cc + 1] = acc[mt][nt][3];
        }
    __syncthreads();

    int c4 = (tid & 31) * 4;
    float4 bias;
    bias.x = bih[n0 + c4]     + bhh[n0 + c4];
    bias.y = bih[n0 + c4 + 1] + bhh[n0 + c4 + 1];
    bias.z = bih[n0 + c4 + 2] + bhh[n0 + c4 + 2];
    bias.w = bih[n0 + c4 + 3] + bhh[n0 + c4 + 3];
    for (int r = tid >> 5; r < 128; r += 8) {
        float4 v = *reinterpret_cast<const float4*>(&stage[r * 132 + c4]);
        v.x += bias.x; v.y += bias.y; v.z += bias.z; v.w += bias.w;
        *reinterpret_cast<float4*>(&C[(size_t)(m0 + r) * G4 + n0 + c4]) = v;
    }
}

// ---------------- persistent bidirectional LSTM ----------------
__device__ __forceinline__ float sigf(float x) { return 1.0f / (1.0f + expf(-x)); }

#define RED_STRIDE 34

__global__ __launch_bounds__(256) void lstm_kernel(
    const float* __restrict__ preF, const float* __restrict__ preB,
    const float* __restrict__ whhF, const float* __restrict__ whhB,
    float* __restrict__ out, float* __restrict__ hbase,
    unsigned* __restrict__ ctr)
{
    extern __shared__ float smf[];
    float* ws  = smf;
    float* hs  = smf + HH * BB;
    float* red = smf + 2 * HH * BB;

    const int tid = threadIdx.x;
    const int dir = blockIdx.x >> 6;
    const int blk = blockIdx.x & 63;
    const int j0  = blk * 8;

    const float* pre = dir ? preB : preF;
    const float* whh = dir ? whhB : whhF;
    float* hb = hbase + dir * (2 * HH * BB);
    unsigned* myctr = ctr + dir;

    for (int i = tid; i < HH * 32; i += 256) {
        int c = i >> 9;
        int k = i & 511;
        int ng = (c >> 3) * HH + j0 + (c & 7);
        ws[k * 32 + c] = whh[(size_t)ng * HH + k];
    }

    const int kg  = tid >> 6;
    const int t64 = tid & 63;
    const int tb  = (t64 & 7) * 4;
    const int tc  = (t64 >> 3) * 4;
    const int kbeg = kg * 128;
    const int ngb  = (tc >> 3) * HH + j0 + (tc & 7);

    const int uj = tid >> 5;
    const int ub = tid & 31;
    float c_reg = 0.0f;
    __syncthreads();

    for (int s = 0; s < SS; s++) {
        const float* hsrc = hb + (s & 1) * (HH * BB);
        float*       hdst = hb + ((s + 1) & 1) * (HH * BB);

        for (int i = tid * 4; i < HH * BB; i += 1024) {
            float4 v = __ldcg(reinterpret_cast<const float4*>(&hsrc[i]));
            *reinterpret_cast<float4*>(&hs[i]) = v;
        }
        float4 pv0 = make_float4(0.f,0.f,0.f,0.f), pv1 = pv0, pv2 = pv0, pv3 = pv0;
        if (kg == 0) {
            const float* pb = pre + (size_t)s * (BB * G4) + ngb;
            pv0 = __ldcg(reinterpret_cast<const float4*>(pb + (size_t)(tb + 0) * G4));
            pv1 = __ldcg(reinterpret_cast<const float4*>(pb + (size_t)(tb + 1) * G4));
            pv2 = __ldcg(reinterpret_cast<const float4*>(pb + (size_t)(tb + 2) * G4));
            pv3 = __ldcg(reinterpret_cast<const float4*>(pb + (size_t)(tb + 3) * G4));
        }
        __syncthreads();

        unsigned long long acc[4][2];
#pragma unroll
        for (int b = 0; b < 4; b++) { acc[b][0] = 0ull; acc[b][1] = 0ull; }

        const float* hp = hs + kbeg * 32 + tb;
        const float* wp = ws + kbeg * 32 + tc;
#pragma unroll 8
        for (int k = 0; k < 128; k++) {
            float4 h4 = *reinterpret_cast<const float4*>(hp);
            ulonglong2 w2 = *reinterpret_cast<const ulonglong2*>(wp);
            unsigned long long hd;
            hd = p2(h4.x, h4.x); fma2(acc[0][0], hd, w2.x); fma2(acc[0][1], hd, w2.y);
            hd = p2(h4.y, h4.y); fma2(acc[1][0], hd, w2.x); fma2(acc[1][1], hd, w2.y);
            hd = p2(h4.z, h4.z); fma2(acc[2][0], hd, w2.x); fma2(acc[2][1], hd, w2.y);
            hd = p2(h4.w, h4.w); fma2(acc[3][0], hd, w2.x); fma2(acc[3][1], hd, w2.y);
            hp += 32; wp += 32;
        }
        if (kg == 0) {
            acc[0][0] = add2(acc[0][0], p2(pv0.x, pv0.y));
            acc[0][1] = add2(acc[0][1], p2(pv0.z, pv0.w));
            acc[1][0] = add2(acc[1][0], p2(pv1.x, pv1.y));
            acc[1][1] = add2(acc[1][1], p2(pv1.z, pv1.w));
            acc[2][0] = add2(acc[2][0], p2(pv2.x, pv2.y));
            acc[2][1] = add2(acc[2][1], p2(pv2.z, pv2.w));
            acc[3][0] = add2(acc[3][0], p2(pv3.x, pv3.y));
            acc[3][1] = add2(acc[3][1], p2(pv3.z, pv3.w));
        }
#pragma unroll
        for (int b = 0; b < 4; b++) {
            unsigned long long* rp = reinterpret_cast<unsigned long long*>(
                &red[(kg * 32 + tb + b) * RED_STRIDE + tc]);
            rp[0] = acc[b][0];
            rp[1] = acc[b][1];
        }
        __syncthreads();

        float gv[4];
#pragma unroll
        for (int g = 0; g < 4; g++) {
            int c = g * 8 + uj;
            gv[g] = (red[(0 * 32 + ub) * RED_STRIDE + c] +
                     red[(1 * 32 + ub) * RED_STRIDE + c]) +
                    (red[(2 * 32 + ub) * RED_STRIDE + c] +
                     red[(3 * 32 + ub) * RED_STRIDE + c]);
        }
        c_reg = sigf(gv[1]) * c_reg + sigf(gv[0]) * tanhf(gv[2]);
        float hv = sigf(gv[3]) * tanhf(c_reg);

        __stcg(&hdst[(j0 + uj) * 32 + ub], hv);
        int so = dir ? (SS - 1 - s) : s;
        __stcg(&out[((size_t)so * BB + ub) * (2 * HH) + dir * HH + j0 + uj], hv);

        // inter-block barrier: release arrival, acquire spin (no L1-flushing fences)
        __syncthreads();
        if (tid == 0) {
            asm volatile("red.release.gpu.add.u32 [%0], %1;"
                         :: "l"(myctr), "r"(1u) : "memory");
            unsigned target = 64u * (unsigned)(s + 1);
            unsigned v;
            do {
                asm volatile("ld.acquire.gpu.u32 %0, [%1];"
                             : "=r"(v) : "l"(myctr) : "memory");
            } while (v < target);
        }
        __syncthreads();
    }
}

// ---------------- sq ----------------
__global__ void sq_kernel(const float* __restrict__ emb) {
    int gwarp = (blockIdx.x * blockDim.x + threadIdx.x) >> 5;
    int lane  = threadIdx.x & 31;
    if (gwarp >= SS * BB) return;
    const float* rowp = emb + (size_t)gwarp * DD;
    float ssum = 0.0f;
#pragma unroll
    for (int d = lane; d < DD; d += 32) { float v = rowp[d]; ssum += v * v; }
#pragma unroll
    for (int o = 16; o > 0; o >>= 1) ssum += __shfl_down_sync(0xffffffffu, ssum, o);
    if (lane == 0) {
        int s = gwarp >> 5, b = gwarp & 31;
        g_sq[b * SS + s] = ssum;
    }
}

// ---------------- pd + block sums ----------------
__global__ __launch_bounds__(256) void pd_kernel(const float* __restrict__ emb) {
    __shared__ __align__(16) float Ans[64][68];
    __shared__ __align__(16) float Ams[64][68];
    __shared__ float redsm[256];
    const int b  = blockIdx.z;
    const int n0 = blockIdx.y * 64;
    const int m0 = blockIdx.x * 64;
    const int tid = threadIdx.x;
    const int tx = tid & 15, ty = tid >> 4;

    float acc[4][4];
#pragma unroll
    for (int i = 0; i < 4; i++)
#pragma unroll
        for (int j = 0; j < 4; j++) acc[i][j] = 0.0f;

    for (int kc = 0; kc < DD; kc += 64) {
#pragma unroll
        for (int r = 0; r < 4; r++) {
            int idx = tid + r * 256;
            int row = idx >> 4;
            int kf  = (idx & 15) * 4;
            float4 vn = *reinterpret_cast<const float4*>(
                &emb[(((size_t)(n0 + row)) * BB + b) * DD + kc + kf]);
            Ans[kf + 0][row] = vn.x; Ans[kf + 1][row] = vn.y;
            Ans[kf + 2][row] = vn.z; Ans[kf + 3][row] = vn.w;
            float4 vm = *reinterpret_cast<const float4*>(
                &emb[(((size_t)(m0 + row)) * BB + b) * DD + kc + kf]);
            Ams[kf + 0][row] = vm.x; Ams[kf + 1][row] = vm.y;
            Ams[kf + 2][row] = vm.z; Ams[kf + 3][row] = vm.w;
        }
        __syncthreads();
#pragma unroll 8
        for (int kk = 0; kk < 64; kk++) {
            float4 an = *reinterpret_cast<const float4*>(&Ans[kk][ty * 4]);
            float4 am = *reinterpret_cast<const float4*>(&Ams[kk][tx * 4]);
            float av[4] = {an.x, an.y, an.z, an.w};
            float bv[4] = {am.x, am.y, am.z, am.w};
#pragma unroll
            for (int i = 0; i < 4; i++)
#pragma unroll
                for (int j = 0; j < 4; j++) acc[i][j] += av[i] * bv[j];
        }
        __syncthreads();
    }

    float sqn[4], sqm[4];
#pragma unroll
    for (int i = 0; i < 4; i++) sqn[i] = g_sq[b * SS + n0 + ty * 4 + i];
#pragma unroll
    for (int j = 0; j < 4; j++) sqm[j] = g_sq[b * SS + m0 + tx * 4 + j];

    float lsum = 0.0f;
#pragma unroll
    for (int i = 0; i < 4; i++) {
        int n = n0 + ty * 4 + i;
        float* prow = g_pd + (((size_t)b * SS) + n) * SS + m0 + tx * 4;
        float4 v;
        float* vp = &v.x;
#pragma unroll
        for (int j = 0; j < 4; j++) {
            float d2 = fmaxf(sqn[i] + sqm[j] - 2.0f * acc[i][j], 0.0f);
            float pdv = (d2 > 0.0f) ? sqrtf(d2) : 0.0f;
            vp[j] = pdv;
            lsum += pdv;
        }
        *reinterpret_cast<float4*>(prow) = v;
    }

    redsm[tid] = lsum;
    __syncthreads();
    for (int o = 128; o > 0; o >>= 1) {
        if (tid < o) redsm[tid] += redsm[tid + o];
        __syncthreads();
    }
    if (tid == 0)
        g_bsum[blockIdx.z * 64 + blockIdx.y * 8 + blockIdx.x] = redsm[0];
}

__global__ void sum_reduce_kernel() {
    __shared__ double red[256];
    int tid = threadIdx.x;
    double s = 0.0;
    for (int i = tid; i < 2048; i += 256) s += (double)g_bsum[i];
    red[tid] = s;
    __syncthreads();
    for (int o = 128; o > 0; o >>= 1) {
        if (tid < o) red[tid] += red[tid + o];
        __syncthreads();
    }
    if (tid == 0) g_sum = red[0];
}

__device__ __forceinline__ float thresh_sigmoid(float dis) {
    if (dis < -1e-3f) return 0.0f;
    if (dis > 1e-3f)  return 1.0f / (1.0f + __expf(-dis));
    float sv = 1.0f / (1.0f + expf(-dis));
    return (sv < 0.5f) ? 0.0f : sv;
}

__global__ void ww_final_kernel(float* __restrict__ outp) {
    size_t i = (size_t)blockIdx.x * blockDim.x + threadIdx.x;
    if (i >= (size_t)BB * SS * SS) return;
    float mean = (float)(g_sum / (double)((size_t)BB * SS * SS));
    outp[OFF_WW + i] = thresh_sigmoid(mean - g_pd[i]);
}

__global__ __launch_bounds__(256) void wo_kernel(
    const float* __restrict__ emb, const float* __restrict__ op_emb,
    float* __restrict__ outp)
{
    __shared__ float ops[DD * 32];
    int tid = threadIdx.x;
    for (int i = tid; i < DD * 32; i += 256) {
        int d = i >> 5, o = i & 31;
        ops[d * 32 + o] = op_emb[o * DD + d];
    }
    __syncthreads();
    int r = tid >> 5, o = tid & 31;
    int gr = blockIdx.x * 8 + r;
    int b = gr >> 9, n = gr & 511;
    const float* erow = emb + (((size_t)n * BB) + b) * DD;
    float acc = 0.0f;
#pragma unroll 16
    for (int d = 0; d < DD; d++) acc += erow[d] * ops[d * 32 + o];
    outp[OFF_WO + (size_t)gr * 32 + o] = thresh_sigmoid(acc);
}

__global__ void pade_kernel(float* __restrict__ outp) {
    size_t i = (size_t)blockIdx.x * blockDim.x + threadIdx.x;
    if (i >= (size_t)SS * BB * HH) return;
    size_t s = i / (BB * HH);
    size_t r = i % (BB * HH);
    size_t b = r / HH, j = r % HH;
    size_t base = (s * BB + b) * (2 * HH);
    outp[OFF_PADE + i] = g_out1[base + j] + g_out1[base + HH + j];
}

__global__ void prob_kernel(float* __restrict__ outp) {
    int i = blockIdx.x * blockDim.x + threadIdx.x;
    if (i >= BB * HH) return;
    int b = i / HH, j = i % HH;
    outp[OFF_PROB + i] =
        g_out1[(((size_t)(SS - 1) * BB) + b) * (2 * HH) + j] +
        g_out1[((size_t)b) * (2 * HH) + HH + j];
}

// ---------------------------------------------------------------------------
extern "C" void kernel_launch(void* const* d_in, const int* in_sizes, int n_in,
                              void* d_out, int out_size)
{
    const float* emb    = (const float*)d_in[0];
    const float* op_emb = (const float*)d_in[2];
    const float* wih0f = (const float*)d_in[3],  *whh0f = (const float*)d_in[4];
    const float* bih0f = (const float*)d_in[5],  *bhh0f = (const float*)d_in[6];
    const float* wih0b = (const float*)d_in[7],  *whh0b = (const float*)d_in[8];
    const float* bih0b = (const float*)d_in[9],  *bhh0b = (const float*)d_in[10];
    const float* wih1f = (const float*)d_in[11], *whh1f = (const float*)d_in[12];
    const float* bih1f = (const float*)d_in[13], *bhh1f = (const float*)d_in[14];
    const float* wih1b = (const float*)d_in[15], *whh1b = (const float*)d_in[16];
    const float* bih1b = (const float*)d_in[17], *bhh1b = (const float*)d_in[18];
    float* outp = (float*)d_out;

    void *pPreF, *pPreB, *pOut0, *pOut1, *pH, *pCtr;
    void *pAhi, *pAlo, *pWhi, *pWlo;
    cudaGetSymbolAddress(&pPreF, g_preF);
    cudaGetSymbolAddress(&pPreB, g_preB);
    cudaGetSymbolAddress(&pOut0, g_out0);
    cudaGetSymbolAddress(&pOut1, g_out1);
    cudaGetSymbolAddress(&pH,    g_h);
    cudaGetSymbolAddress(&pCtr,  g_ctr);
    cudaGetSymbolAddress(&pAhi,  g_Ahi);
    cudaGetSymbolAddress(&pAlo,  g_Alo);
    cudaGetSymbolAddress(&pWhi,  g_Whi);
    cudaGetSymbolAddress(&pWlo,  g_Wlo);
    float* preF = (float*)pPreF;  float* preB = (float*)pPreB;
    float* out0 = (float*)pOut0;  float* out1 = (float*)pOut1;
    float* hb   = (float*)pH;     unsigned* ctr = (unsigned*)pCtr;
    __nv_bfloat16* Ahi = (__nv_bfloat16*)pAhi;
    __nv_bfloat16* Alo = (__nv_bfloat16*)pAlo;
    __nv_bfloat16* Whi = (__nv_bfloat16*)pWhi;
    __nv_bfloat16* Wlo = (__nv_bfloat16*)pWlo;

    const int SMEM_LSTM =
        (2 * HH * BB + 4 * 32 * RED_STRIDE) * (int)sizeof(float);
    cudaFuncSetAttribute(lstm_kernel,
        cudaFuncAttributeMaxDynamicSharedMemorySize, SMEM_LSTM);
    const int SMEM_MMA = 1024 + 2 * 65536;   // align slack + double buffer
    cudaFuncSetAttribute(mma_pre_kernel,
        cudaFuncAttributeMaxDynamicSharedMemorySize, SMEM_MMA);

    init_kernel<<<512, 256>>>();

    dim3 ggrid(16, 128);
    // ---- layer 0 (K = 128) ----
    split_kernel<<<16384 * 128 / 1024, 256>>>(emb, Ahi, Alo, 16384 * 128);
    split_kernel<<<2048 * 128 / 1024, 256>>>(wih0f, Whi, Wlo, 2048 * 128);
    mma_pre_kernel<<<ggrid, 256, SMEM_MMA>>>(Ahi, Alo, Whi, Wlo,
                                             bih0f, bhh0f, preF, 128, 0);
    split_kernel<<<2048 * 128 / 1024, 256>>>(wih0b, Whi, Wlo, 2048 * 128);
    mma_pre_kernel<<<ggrid, 256, SMEM_MMA>>>(Ahi, Alo, Whi, Wlo,
                                             bih0b, bhh0b, preB, 128, 1);
    lstm_kernel<<<128, 256, SMEM_LSTM>>>(preF, preB, whh0f, whh0b,
                                         out0, hb, ctr);
    // ---- layer 1 (K = 1024) ----
    split_kernel<<<16384 * 1024 / 1024, 256>>>(out0, Ahi, Alo, 16384 * 1024);
    split_kernel<<<2048 * 1024 / 1024, 256>>>(wih1f, Whi, Wlo, 2048 * 1024);
    mma_pre_kernel<<<ggrid, 256, SMEM_MMA>>>(Ahi, Alo, Whi, Wlo,
                                             bih1f, bhh1f, preF, 1024, 0);
    split_kernel<<<2048 * 1024 / 1024, 256>>>(wih1b, Whi, Wlo, 2048 * 1024);
    mma_pre_kernel<<<ggrid, 256, SMEM_MMA>>>(Ahi, Alo, Whi, Wlo,
                                             bih1b, bhh1b, preB, 1024, 1);
    lstm_kernel<<<128, 256, SMEM_LSTM>>>(preF, preB, whh1f, whh1b,
                                         out1, hb + 2 * 2 * HH * BB, ctr + 2);

    // ---- tails ----
    sq_kernel<<<(SS * BB * 32 + 255) / 256, 256>>>(emb);
    dim3 pgrid(8, 8, 32);
    pd_kernel<<<pgrid, 256>>>(emb);
    sum_reduce_kernel<<<1, 256>>>();
    ww_final_kernel<<<32768, 256>>>(outp);
    wo_kernel<<<2048, 256>>>(emb, op_emb, outp);
    pade_kernel<<<32768, 256>>>(outp);
    prob_kernel<<<64, 256>>>(outp);
}